// round 15
// baseline (speedup 1.0000x reference)
#include <cuda_runtime.h>
#include <cuda_bf16.h>
#include <math.h>
#include <cstdint>

// Problem constants
#define NN 100000      // nodes
#define FF 128         // node features
#define HH 128         // hidden
#define EE 1600000     // edges
#define BB 65536       // queries
#define TD 64          // H/2
#define PIN 448        // 2H + H + TD
#define NHALF 50048    // 391 * 128 (row-split point)

#define SCAN_B 1024
#define NBLK_SCAN ((NN + SCAN_B - 1) / SCAN_B)   // 98

// bf16 transposed-weight pool offsets (Wt[n][k], row stride = K)
#define OFF_W1  0
#define OFF_W2  16384
#define OFF_W3  32768
#define OFF_WF  49152
#define OFF_WH1 65536          // 256 rows x 448
#define OFF_WH2 180224         // 128 rows x 256
#define OFF_WH3 212992         // 64 rows x 128
#define WT_TOTAL 221184

#define LDBYTES 144
#define ZLD1 528               // z1 row stride (256 bf16 + 16B pad)
#define ZLD2 272               // z2 row stride (128 bf16 + 16B pad)
#define HF_SMEM (2 * 128 * LDBYTES + 128 * ZLD1)   // 104448

// ---------------- scratch (static device memory; no allocation) --------------
__device__ float g_dinv[NN];
__device__ int   g_cnt  [NN];
__device__ int   g_rowp [NN + 1];
__device__ int   g_cursor[NN];
__device__ int   g_bsum [NBLK_SCAN + 1];
__device__ int   g_csr_src [EE];
__device__ __nv_bfloat16 g_wt  [WT_TOTAL];
__device__ __nv_bfloat16 g_hw  [(size_t)NN * HH];   // rotation buffer 0
__device__ __nv_bfloat16 g_h   [(size_t)NN * HH];   // rotation buffer 1
__device__ __nv_bfloat16 g_hw2 [(size_t)NN * HH];   // rotation buffer 2
__device__ __nv_bfloat16 g_temp[(size_t)BB * HH];

// ======================= HMMA helpers ========================================
__device__ __forceinline__ uint32_t smem_to_u32(const void* p) {
    uint32_t a;
    asm("{ .reg .u64 t; cvta.to.shared.u64 t, %1; cvt.u32.u64 %0, t; }"
        : "=r"(a) : "l"(p));
    return a;
}
__device__ __forceinline__ void ldm_x4(uint32_t& r0, uint32_t& r1,
                                       uint32_t& r2, uint32_t& r3, uint32_t addr) {
    asm volatile("ldmatrix.sync.aligned.m8n8.x4.shared.b16 {%0,%1,%2,%3}, [%4];"
        : "=r"(r0), "=r"(r1), "=r"(r2), "=r"(r3) : "r"(addr));
}
__device__ __forceinline__ void mma_bf16(float* c, const uint32_t* a,
                                         uint32_t b0, uint32_t b1) {
    asm volatile(
        "mma.sync.aligned.m16n8k16.row.col.f32.bf16.bf16.f32 "
        "{%0,%1,%2,%3}, {%4,%5,%6,%7}, {%8,%9}, {%0,%1,%2,%3};"
        : "+f"(c[0]), "+f"(c[1]), "+f"(c[2]), "+f"(c[3])
        : "r"(a[0]), "r"(a[1]), "r"(a[2]), "r"(a[3]), "r"(b0), "r"(b1));
}

// ============ weight transpose + bf16 convert (once per launch) ==============
struct WtSeg { const float* src; int K; int N; int off; };
struct WtParams { WtSeg seg[7]; };

__global__ void wt_build_kernel(WtParams P, __nv_bfloat16* wt) {
    int idx = blockIdx.x * blockDim.x + threadIdx.x;
    if (idx >= WT_TOTAL) return;
    #pragma unroll
    for (int s = 0; s < 7; s++) {
        int sz = P.seg[s].K * P.seg[s].N;
        if (idx < P.seg[s].off + sz) {
            int li = idx - P.seg[s].off;
            int K = P.seg[s].K;
            int n = li / K, k = li - n * K;
            wt[idx] = __float2bfloat16(P.seg[s].src[(size_t)k * P.seg[s].N + n]);
            return;
        }
    }
}

// ======================= generic tensor-core GEMM ============================
// C[M, Ntot] = A[M, K] @ W[K, Ntot]; Wt is bf16 transposed: Wt[n][k], stride K.
// ASRC: 0 = fp32 dense, 1 = bf16 dense, 3 = tin gather
// mode 0: C = v   mode 1: C = relu(v + bias)   mode 2: C = v * dinv[row]
// rowStart: base row offset (for row-range pipelined launches)
struct GParams {
    const void* A;
    const __nv_bfloat16* h;
    const __nv_bfloat16* temp;
    const float* day_table; const float* time_table; const float* mode_table;
    const int* orig; const int* dest; const int* day_ids; const int* time_ids;
    const int* mode_ids;
};

template<int ASRC>
__global__ void __launch_bounds__(256, 2)
tc_gemm_kernel(GParams P, const __nv_bfloat16* __restrict__ Wt,
               const float* __restrict__ bias, const float* __restrict__ dinv,
               __nv_bfloat16* __restrict__ C,
               int M, int K, int Ntot, int mode, int rowStart) {
    __shared__ __align__(16) char smem[2 * 128 * LDBYTES];
    char* sA = smem;
    char* sB = smem + 128 * LDBYTES;
    uint32_t sAu = smem_to_u32(sA);
    uint32_t sBu = smem_to_u32(sB);

    int tid = threadIdx.x;
    int wid = tid >> 5;
    int lane = tid & 31;
    int wm = wid >> 1;
    int wn = wid & 1;

    int rowBase = rowStart + blockIdx.y * 128;
    int colBase = blockIdx.x * 128;

    float acc[2][8][4];
    #pragma unroll
    for (int mt = 0; mt < 2; mt++)
        #pragma unroll
        for (int nf = 0; nf < 8; nf++)
            #pragma unroll
            for (int j = 0; j < 4; j++) acc[mt][nf][j] = 0.0f;

    int lq = lane & 15;
    int lh = lane >> 4;

    for (int k0 = 0; k0 < K; k0 += 64) {
        __syncthreads();
        if (ASRC == 0) {
            const float* A = (const float*)P.A;
            #pragma unroll 4
            for (int i = tid; i < 128 * 32; i += 256) {
                int r = i >> 5, kp = i & 31;
                int gr = rowBase + r;
                float2 v = make_float2(0.f, 0.f);
                if (gr < M) v = *(const float2*)(A + (size_t)gr * K + k0 + 2 * kp);
                *(__nv_bfloat162*)(sA + r * LDBYTES + kp * 4) = __float22bfloat162_rn(v);
            }
        } else if (ASRC == 1) {
            const __nv_bfloat16* A = (const __nv_bfloat16*)P.A;
            #pragma unroll 4
            for (int i = tid; i < 128 * 8; i += 256) {
                int r = i >> 3, seg = i & 7;
                int gr = rowBase + r;
                uint4 v = make_uint4(0, 0, 0, 0);
                if (gr < M) v = *(const uint4*)(A + (size_t)gr * K + k0 + seg * 8);
                *(uint4*)(sA + r * LDBYTES + seg * 16) = v;
            }
        } else {
            #pragma unroll 4
            for (int i = tid; i < 128 * 32; i += 256) {
                int r = i >> 5, kp = i & 31;
                int gr = rowBase + r;
                const float* srcp = (k0 == 0)
                    ? P.day_table  + (size_t)P.day_ids[gr]  * TD
                    : P.time_table + (size_t)P.time_ids[gr] * TD;
                float2 v = *(const float2*)(srcp + 2 * kp);
                *(__nv_bfloat162*)(sA + r * LDBYTES + kp * 4) = __float22bfloat162_rn(v);
            }
        }
        #pragma unroll 4
        for (int i = tid; i < 128 * 8; i += 256) {
            int n = i >> 3, seg = i & 7;
            int gc = colBase + n;
            uint4 v = make_uint4(0, 0, 0, 0);
            if (gc < Ntot) v = *(const uint4*)(Wt + (size_t)gc * K + k0 + seg * 8);
            *(uint4*)(sB + n * LDBYTES + seg * 16) = v;
        }
        __syncthreads();

        #pragma unroll
        for (int ks = 0; ks < 4; ks++) {
            uint32_t af[2][4];
            #pragma unroll
            for (int mt = 0; mt < 2; mt++) {
                uint32_t addr = sAu + (uint32_t)(wm * 32 + mt * 16 + lq) * LDBYTES
                              + ks * 32 + lh * 16;
                ldm_x4(af[mt][0], af[mt][1], af[mt][2], af[mt][3], addr);
            }
            uint32_t bfr[8][2];
            #pragma unroll
            for (int g = 0; g < 4; g++) {
                uint32_t r0, r1, r2, r3;
                uint32_t addr = sBu + (uint32_t)(wn * 64 + g * 16 + lq) * LDBYTES
                              + ks * 32 + lh * 16;
                ldm_x4(r0, r1, r2, r3, addr);
                bfr[2 * g][0] = r0;     bfr[2 * g][1] = r2;
                bfr[2 * g + 1][0] = r1; bfr[2 * g + 1][1] = r3;
            }
            #pragma unroll
            for (int mt = 0; mt < 2; mt++)
                #pragma unroll
                for (int nf = 0; nf < 8; nf++)
                    mma_bf16(acc[mt][nf], af[mt], bfr[nf][0], bfr[nf][1]);
        }
    }

    int rowOff = lane >> 2;
    int colOff = (lane & 3) * 2;
    #pragma unroll
    for (int mt = 0; mt < 2; mt++) {
        #pragma unroll
        for (int half = 0; half < 2; half++) {
            int r = rowBase + wm * 32 + mt * 16 + rowOff + half * 8;
            if (r >= M) continue;
            float dsc = (mode == 2) ? dinv[r] : 1.0f;
            #pragma unroll
            for (int nf = 0; nf < 8; nf++) {
                int c = colBase + wn * 64 + nf * 8 + colOff;
                if (c >= Ntot) continue;
                float v0 = acc[mt][nf][half * 2 + 0];
                float v1 = acc[mt][nf][half * 2 + 1];
                if (mode == 1) {
                    v0 = fmaxf(v0 + bias[c], 0.f);
                    v1 = fmaxf(v1 + bias[c + 1], 0.f);
                } else if (mode == 2) {
                    v0 *= dsc;
                    v1 *= dsc;
                }
                *(__nv_bfloat162*)(C + (size_t)r * Ntot + c) =
                    __float22bfloat162_rn(make_float2(v0, v1));
            }
        }
    }
}

// ======================= fully fused prediction head =========================
__global__ void __launch_bounds__(256, 2)
head_fused_kernel(GParams P,
                  const __nv_bfloat16* __restrict__ WtH1,
                  const __nv_bfloat16* __restrict__ WtH2,
                  const __nv_bfloat16* __restrict__ WtH3,
                  const float* __restrict__ bh1, const float* __restrict__ bh2,
                  const float* __restrict__ bh3,
                  const float* __restrict__ w4, const float* __restrict__ b4,
                  float* __restrict__ outp) {
    extern __shared__ __align__(16) char smem[];
    char* sA = smem;
    char* sB = smem + 128 * LDBYTES;
    char* sZ = smem + 2 * 128 * LDBYTES;
    uint32_t sAu = smem_to_u32(sA);
    uint32_t sBu = smem_to_u32(sB);
    uint32_t sZu = smem_to_u32(sZ);

    int tid = threadIdx.x;
    int wid = tid >> 5;
    int lane = tid & 31;
    int wm = wid >> 1;
    int wn = wid & 1;
    int rowBase = blockIdx.x * 128;

    int lq = lane & 15;
    int lh = lane >> 4;
    int rowOff = lane >> 2;
    int colOff = (lane & 3) * 2;

    float acc[2][8][4];

    // ================= Pass 1: z1 = relu(comb @ Wh1 + bh1) ==================
    #pragma unroll 1
    for (int nh = 0; nh < 2; nh++) {
        #pragma unroll
        for (int mt = 0; mt < 2; mt++)
            #pragma unroll
            for (int nf = 0; nf < 8; nf++)
                #pragma unroll
                for (int j = 0; j < 4; j++) acc[mt][nf][j] = 0.0f;

        #pragma unroll 1
        for (int kc = 0; kc < 7; kc++) {
            int k0 = kc << 6;
            __syncthreads();
            if (k0 < 384) {
                #pragma unroll 4
                for (int i = tid; i < 128 * 8; i += 256) {
                    int r = i >> 3, seg = i & 7;
                    int gr = rowBase + r;
                    const __nv_bfloat16* srcp;
                    if (k0 < 128)       srcp = P.h + (size_t)P.orig[gr] * HH + k0;
                    else if (k0 < 256)  srcp = P.h + (size_t)P.dest[gr] * HH + (k0 - 128);
                    else                srcp = P.temp + (size_t)gr * HH + (k0 - 256);
                    *(uint4*)(sA + r * LDBYTES + seg * 16) = *(const uint4*)(srcp + seg * 8);
                }
            } else {
                #pragma unroll 4
                for (int i = tid; i < 128 * 32; i += 256) {
                    int r = i >> 5, kp = i & 31;
                    int gr = rowBase + r;
                    const float* srcp = P.mode_table + (size_t)P.mode_ids[gr] * TD;
                    float2 v = *(const float2*)(srcp + 2 * kp);
                    *(__nv_bfloat162*)(sA + r * LDBYTES + kp * 4) = __float22bfloat162_rn(v);
                }
            }
            #pragma unroll 4
            for (int i = tid; i < 128 * 8; i += 256) {
                int n = i >> 3, seg = i & 7;
                uint4 v = *(const uint4*)(WtH1 + (size_t)(nh * 128 + n) * 448 + k0 + seg * 8);
                *(uint4*)(sB + n * LDBYTES + seg * 16) = v;
            }
            __syncthreads();

            #pragma unroll
            for (int ks = 0; ks < 4; ks++) {
                uint32_t af[2][4];
                #pragma unroll
                for (int mt = 0; mt < 2; mt++) {
                    uint32_t addr = sAu + (uint32_t)(wm * 32 + mt * 16 + lq) * LDBYTES
                                  + ks * 32 + lh * 16;
                    ldm_x4(af[mt][0], af[mt][1], af[mt][2], af[mt][3], addr);
                }
                uint32_t bfr[8][2];
                #pragma unroll
                for (int g = 0; g < 4; g++) {
                    uint32_t r0, r1, r2, r3;
                    uint32_t addr = sBu + (uint32_t)(wn * 64 + g * 16 + lq) * LDBYTES
                                  + ks * 32 + lh * 16;
                    ldm_x4(r0, r1, r2, r3, addr);
                    bfr[2 * g][0] = r0;     bfr[2 * g][1] = r2;
                    bfr[2 * g + 1][0] = r1; bfr[2 * g + 1][1] = r3;
                }
                #pragma unroll
                for (int mt = 0; mt < 2; mt++)
                    #pragma unroll
                    for (int nf = 0; nf < 8; nf++)
                        mma_bf16(acc[mt][nf], af[mt], bfr[nf][0], bfr[nf][1]);
            }
        }
        #pragma unroll
        for (int mt = 0; mt < 2; mt++)
            #pragma unroll
            for (int half = 0; half < 2; half++) {
                int r = wm * 32 + mt * 16 + rowOff + half * 8;
                #pragma unroll
                for (int nf = 0; nf < 8; nf++) {
                    int c = wn * 64 + nf * 8 + colOff;
                    float v0 = fmaxf(acc[mt][nf][half * 2 + 0] + bh1[nh * 128 + c], 0.f);
                    float v1 = fmaxf(acc[mt][nf][half * 2 + 1] + bh1[nh * 128 + c + 1], 0.f);
                    *(__nv_bfloat162*)(sZ + r * ZLD1 + (nh * 128 + c) * 2) =
                        __float22bfloat162_rn(make_float2(v0, v1));
                }
            }
    }

    // ================= Pass 2: z2 = relu(z1 @ Wh2 + bh2) ====================
    #pragma unroll
    for (int mt = 0; mt < 2; mt++)
        #pragma unroll
        for (int nf = 0; nf < 8; nf++)
            #pragma unroll
            for (int j = 0; j < 4; j++) acc[mt][nf][j] = 0.0f;

    #pragma unroll 1
    for (int kc = 0; kc < 4; kc++) {
        int k0 = kc << 6;
        __syncthreads();
        #pragma unroll 4
        for (int i = tid; i < 128 * 8; i += 256) {
            int n = i >> 3, seg = i & 7;
            uint4 v = *(const uint4*)(WtH2 + (size_t)n * 256 + k0 + seg * 8);
            *(uint4*)(sB + n * LDBYTES + seg * 16) = v;
        }
        __syncthreads();

        #pragma unroll
        for (int ks = 0; ks < 4; ks++) {
            uint32_t af[2][4];
            #pragma unroll
            for (int mt = 0; mt < 2; mt++) {
                uint32_t addr = sZu + (uint32_t)(wm * 32 + mt * 16 + lq) * ZLD1
                              + kc * 128 + ks * 32 + lh * 16;
                ldm_x4(af[mt][0], af[mt][1], af[mt][2], af[mt][3], addr);
            }
            uint32_t bfr[8][2];
            #pragma unroll
            for (int g = 0; g < 4; g++) {
                uint32_t r0, r1, r2, r3;
                uint32_t addr = sBu + (uint32_t)(wn * 64 + g * 16 + lq) * LDBYTES
                              + ks * 32 + lh * 16;
                ldm_x4(r0, r1, r2, r3, addr);
                bfr[2 * g][0] = r0;     bfr[2 * g][1] = r2;
                bfr[2 * g + 1][0] = r1; bfr[2 * g + 1][1] = r3;
            }
            #pragma unroll
            for (int mt = 0; mt < 2; mt++)
                #pragma unroll
                for (int nf = 0; nf < 8; nf++)
                    mma_bf16(acc[mt][nf], af[mt], bfr[nf][0], bfr[nf][1]);
        }
    }
    __syncthreads();
    #pragma unroll
    for (int mt = 0; mt < 2; mt++)
        #pragma unroll
        for (int half = 0; half < 2; half++) {
            int r = wm * 32 + mt * 16 + rowOff + half * 8;
            #pragma unroll
            for (int nf = 0; nf < 8; nf++) {
                int c = wn * 64 + nf * 8 + colOff;
                float v0 = fmaxf(acc[mt][nf][half * 2 + 0] + bh2[c], 0.f);
                float v1 = fmaxf(acc[mt][nf][half * 2 + 1] + bh2[c + 1], 0.f);
                *(__nv_bfloat162*)(sZ + r * ZLD2 + c * 2) =
                    __float22bfloat162_rn(make_float2(v0, v1));
            }
        }

    // ============ Pass 3: z3 = relu(z2 @ Wh3 + bh3); dot Wh4; sigmoid =======
    #pragma unroll
    for (int mt = 0; mt < 2; mt++)
        #pragma unroll
        for (int nf = 0; nf < 8; nf++)
            #pragma unroll
            for (int j = 0; j < 4; j++) acc[mt][nf][j] = 0.0f;

    #pragma unroll 1
    for (int kc = 0; kc < 2; kc++) {
        int k0 = kc << 6;
        __syncthreads();
        #pragma unroll 4
        for (int i = tid; i < 128 * 8; i += 256) {
            int n = i >> 3, seg = i & 7;
            uint4 v = make_uint4(0, 0, 0, 0);
            if (n < 64) v = *(const uint4*)(WtH3 + (size_t)n * 128 + k0 + seg * 8);
            *(uint4*)(sB + n * LDBYTES + seg * 16) = v;
        }
        __syncthreads();

        #pragma unroll
        for (int ks = 0; ks < 4; ks++) {
            uint32_t af[2][4];
            #pragma unroll
            for (int mt = 0; mt < 2; mt++) {
                uint32_t addr = sZu + (uint32_t)(wm * 32 + mt * 16 + lq) * ZLD2
                              + kc * 128 + ks * 32 + lh * 16;
                ldm_x4(af[mt][0], af[mt][1], af[mt][2], af[mt][3], addr);
            }
            uint32_t bfr[8][2];
            #pragma unroll
            for (int g = 0; g < 4; g++) {
                uint32_t r0, r1, r2, r3;
                uint32_t addr = sBu + (uint32_t)(wn * 64 + g * 16 + lq) * LDBYTES
                              + ks * 32 + lh * 16;
                ldm_x4(r0, r1, r2, r3, addr);
                bfr[2 * g][0] = r0;     bfr[2 * g][1] = r2;
                bfr[2 * g + 1][0] = r1; bfr[2 * g + 1][1] = r3;
            }
            #pragma unroll
            for (int mt = 0; mt < 2; mt++)
                #pragma unroll
                for (int nf = 0; nf < 8; nf++)
                    mma_bf16(acc[mt][nf], af[mt], bfr[nf][0], bfr[nf][1]);
        }
    }

    #pragma unroll
    for (int mt = 0; mt < 2; mt++)
        #pragma unroll
        for (int half = 0; half < 2; half++) {
            int r = rowBase + wm * 32 + mt * 16 + rowOff + half * 8;
            float part = 0.0f;
            if (wn == 0) {
                #pragma unroll
                for (int nf = 0; nf < 8; nf++) {
                    int c = nf * 8 + colOff;
                    float v0 = fmaxf(acc[mt][nf][half * 2 + 0] + bh3[c], 0.f);
                    float v1 = fmaxf(acc[mt][nf][half * 2 + 1] + bh3[c + 1], 0.f);
                    part = fmaf(v0, w4[c], part);
                    part = fmaf(v1, w4[c + 1], part);
                }
            }
            part += __shfl_xor_sync(0xFFFFFFFFu, part, 1);
            part += __shfl_xor_sync(0xFFFFFFFFu, part, 2);
            if (wn == 0 && (lane & 3) == 0) {
                float v = part + b4[0];
                outp[r] = 1.0f / (1.0f + expf(-v));
            }
        }
}

// ======================= CSR build ===========================================
__global__ void cnt_count_kernel(const int* __restrict__ dst, int* cnt) {
    int i = blockIdx.x * blockDim.x + threadIdx.x;
    int e = i * 8;
    if (e + 7 < EE) {
        int4 d0 = *(const int4*)(dst + e);
        int4 d1 = *(const int4*)(dst + e + 4);
        atomicAdd(&cnt[d0.x], 1); atomicAdd(&cnt[d0.y], 1);
        atomicAdd(&cnt[d0.z], 1); atomicAdd(&cnt[d0.w], 1);
        atomicAdd(&cnt[d1.x], 1); atomicAdd(&cnt[d1.y], 1);
        atomicAdd(&cnt[d1.z], 1); atomicAdd(&cnt[d1.w], 1);
    } else {
        for (int k = e; k < EE; k++) atomicAdd(&cnt[dst[k]], 1);
    }
}
__global__ void dinv_kernel(const int* __restrict__ cnt, float* dinv) {
    int i = blockIdx.x * blockDim.x + threadIdx.x;
    if (i < NN) dinv[i] = rsqrtf((float)cnt[i] + 1.0f);
}
__global__ void scan_block_kernel(const int* __restrict__ cnt, int* excl, int* bsum) {
    __shared__ int s[SCAN_B];
    int tid = threadIdx.x;
    int i = blockIdx.x * SCAN_B + tid;
    int v = (i < NN) ? cnt[i] : 0;
    s[tid] = v;
    __syncthreads();
    for (int off = 1; off < SCAN_B; off <<= 1) {
        int t = (tid >= off) ? s[tid - off] : 0;
        __syncthreads();
        s[tid] += t;
        __syncthreads();
    }
    if (i < NN) excl[i] = s[tid] - v;
    if (tid == SCAN_B - 1) bsum[blockIdx.x] = s[tid];
}
__global__ void scan_bsum_kernel(int* bsum) {
    __shared__ int s[NBLK_SCAN];
    int tid = threadIdx.x;
    if (tid < NBLK_SCAN) s[tid] = bsum[tid];
    __syncthreads();
    if (tid == 0) {
        int run = 0;
        for (int b = 0; b < NBLK_SCAN; b++) { int t = s[b]; s[b] = run; run += t; }
    }
    __syncthreads();
    if (tid < NBLK_SCAN) bsum[tid] = s[tid];
}
__global__ void scan_add_kernel(int* rowp, const int* __restrict__ bsum, int* cursor) {
    int i = blockIdx.x * blockDim.x + threadIdx.x;
    if (i < NN) {
        int v = rowp[i] + bsum[i / SCAN_B];
        rowp[i] = v;
        cursor[i] = v;
    }
    if (i == 0) rowp[NN] = EE;
}
__global__ void scatter_kernel(const int* __restrict__ src, const int* __restrict__ dst,
                               int* cursor, int* csr_src) {
    int i = blockIdx.x * blockDim.x + threadIdx.x;
    int e = i * 8;
    if (e + 7 < EE) {
        int4 s0 = *(const int4*)(src + e);
        int4 d0 = *(const int4*)(dst + e);
        int4 s1 = *(const int4*)(src + e + 4);
        int4 d1 = *(const int4*)(dst + e + 4);
        int p0 = atomicAdd(&cursor[d0.x], 1);
        int p1 = atomicAdd(&cursor[d0.y], 1);
        int p2 = atomicAdd(&cursor[d0.z], 1);
        int p3 = atomicAdd(&cursor[d0.w], 1);
        int p4 = atomicAdd(&cursor[d1.x], 1);
        int p5 = atomicAdd(&cursor[d1.y], 1);
        int p6 = atomicAdd(&cursor[d1.z], 1);
        int p7 = atomicAdd(&cursor[d1.w], 1);
        csr_src[p0] = s0.x; csr_src[p1] = s0.y;
        csr_src[p2] = s0.z; csr_src[p3] = s0.w;
        csr_src[p4] = s1.x; csr_src[p5] = s1.y;
        csr_src[p6] = s1.z; csr_src[p7] = s1.w;
    } else {
        for (int k = e; k < EE; k++)
            csr_src[atomicAdd(&cursor[dst[k]], 1)] = src[k];
    }
}

// ====== fused aggregation over node range [nodeStart, nodeEnd) ===============
__global__ void __launch_bounds__(256)
agg_fused_kernel(const int* __restrict__ rowp,
                 const int* __restrict__ csr_src,
                 const float* __restrict__ dinv,
                 const __nv_bfloat16* __restrict__ u,
                 const float* __restrict__ bias,
                 __nv_bfloat16* __restrict__ h,
                 int nodeStart, int nodeEnd) {
    int node = nodeStart + ((blockIdx.x * blockDim.x + threadIdx.x) >> 5);
    if (node >= nodeEnd) return;
    int lane = threadIdx.x & 31;
    int col = lane * 4;

    int beg = rowp[node], end = rowp[node + 1];
    float a0 = 0.f, a1 = 0.f, a2 = 0.f, a3 = 0.f;
    for (int i = beg; i < end; i += 32) {
        int n = end - i; if (n > 32) n = 32;
        int sidx = 0;
        if (lane < n) sidx = csr_src[i + lane];
        #pragma unroll 4
        for (int j = 0; j < n; j++) {
            int s = __shfl_sync(0xFFFFFFFFu, sidx, j);
            uint2 raw = *(const uint2*)(u + (size_t)s * HH + col);
            float2 f0 = __bfloat1622float2(*(__nv_bfloat162*)&raw.x);
            float2 f1 = __bfloat1622float2(*(__nv_bfloat162*)&raw.y);
            a0 += f0.x; a1 += f0.y; a2 += f1.x; a3 += f1.y;
        }
    }
    uint2 raws = *(const uint2*)(u + (size_t)node * HH + col);
    float2 fs0 = __bfloat1622float2(*(__nv_bfloat162*)&raws.x);
    float2 fs1 = __bfloat1622float2(*(__nv_bfloat162*)&raws.y);
    a0 += fs0.x; a1 += fs0.y; a2 += fs1.x; a3 += fs1.y;

    float di = dinv[node];
    const float4 b = *(const float4*)(bias + col);
    a0 = fmaxf(fmaf(a0, di, b.x), 0.f);
    a1 = fmaxf(fmaf(a1, di, b.y), 0.f);
    a2 = fmaxf(fmaf(a2, di, b.z), 0.f);
    a3 = fmaxf(fmaf(a3, di, b.w), 0.f);
    uint2 outv;
    *(__nv_bfloat162*)&outv.x = __float22bfloat162_rn(make_float2(a0, a1));
    *(__nv_bfloat162*)&outv.y = __float22bfloat162_rn(make_float2(a2, a3));
    *(uint2*)(h + (size_t)node * HH + col) = outv;
}

// =============================================================================
extern "C" void kernel_launch(void* const* d_in, const int* in_sizes, int n_in,
                              void* d_out, int out_size) {
    const float* x          = (const float*)d_in[0];
    const int*   edge_index = (const int*)  d_in[1];
    const int*   origin_ids = (const int*)  d_in[2];
    const int*   dest_ids   = (const int*)  d_in[3];
    const int*   day_ids    = (const int*)  d_in[4];
    const int*   time_ids   = (const int*)  d_in[5];
    const int*   mode_ids   = (const int*)  d_in[6];
    const float* W1 = (const float*)d_in[7];
    const float* b1 = (const float*)d_in[8];
    const float* W2 = (const float*)d_in[9];
    const float* b2 = (const float*)d_in[10];
    const float* W3 = (const float*)d_in[11];
    const float* b3 = (const float*)d_in[12];
    const float* day_table  = (const float*)d_in[13];
    const float* time_table = (const float*)d_in[14];
    const float* mode_table = (const float*)d_in[15];
    const float* Wf  = (const float*)d_in[16];
    const float* bf  = (const float*)d_in[17];
    const float* Wh1 = (const float*)d_in[18];
    const float* bh1 = (const float*)d_in[19];
    const float* Wh2 = (const float*)d_in[20];
    const float* bh2 = (const float*)d_in[21];
    const float* Wh3 = (const float*)d_in[22];
    const float* bh3 = (const float*)d_in[23];
    const float* Wh4 = (const float*)d_in[24];
    const float* bh4 = (const float*)d_in[25];
    float* out = (float*)d_out;

    const int* srcE = edge_index;
    const int* dstE = edge_index + EE;

    float* dinv;
    int *cnt, *rowp, *cursor, *bsum, *csr_src;
    __nv_bfloat16 *wt, *bufA, *bufB, *bufC, *temp;
    cudaGetSymbolAddress((void**)&dinv, g_dinv);
    cudaGetSymbolAddress((void**)&cnt,  g_cnt);
    cudaGetSymbolAddress((void**)&rowp, g_rowp);
    cudaGetSymbolAddress((void**)&cursor, g_cursor);
    cudaGetSymbolAddress((void**)&bsum, g_bsum);
    cudaGetSymbolAddress((void**)&csr_src,  g_csr_src);
    cudaGetSymbolAddress((void**)&wt,   g_wt);
    cudaGetSymbolAddress((void**)&bufA, g_hw);
    cudaGetSymbolAddress((void**)&bufB, g_h);
    cudaGetSymbolAddress((void**)&bufC, g_hw2);
    cudaGetSymbolAddress((void**)&temp, g_temp);

    // --- side stream + events + attributes (created once) ---
    static cudaStream_t sSide = nullptr;
    static cudaEvent_t evRoot = nullptr, evDinv = nullptr, evCSR = nullptr,
                       evA1a = nullptr, evA1b = nullptr, evG2 = nullptr,
                       evA2a = nullptr, evA2b = nullptr, evG3 = nullptr;
    if (!sSide) {
        cudaStreamCreateWithFlags(&sSide, cudaStreamNonBlocking);
        cudaEventCreateWithFlags(&evRoot, cudaEventDisableTiming);
        cudaEventCreateWithFlags(&evDinv, cudaEventDisableTiming);
        cudaEventCreateWithFlags(&evCSR,  cudaEventDisableTiming);
        cudaEventCreateWithFlags(&evA1a, cudaEventDisableTiming);
        cudaEventCreateWithFlags(&evA1b, cudaEventDisableTiming);
        cudaEventCreateWithFlags(&evG2,  cudaEventDisableTiming);
        cudaEventCreateWithFlags(&evA2a, cudaEventDisableTiming);
        cudaEventCreateWithFlags(&evA2b, cudaEventDisableTiming);
        cudaEventCreateWithFlags(&evG3,  cudaEventDisableTiming);
        cudaFuncSetAttribute(head_fused_kernel,
            cudaFuncAttributeMaxDynamicSharedMemorySize, HF_SMEM);
    }

    const int T = 256;
    int e8Blocks = (int)(((size_t)(EE + 7) / 8 + T - 1) / T);

    // ---- fork: CSR build on side stream ----
    cudaEventRecord(evRoot, 0);
    cudaStreamWaitEvent(sSide, evRoot, 0);
    cudaMemsetAsync(cnt, 0, NN * sizeof(int), sSide);
    cnt_count_kernel<<<e8Blocks, T, 0, sSide>>>(dstE, cnt);
    dinv_kernel<<<(NN + T - 1) / T, T, 0, sSide>>>(cnt, dinv);
    cudaEventRecord(evDinv, sSide);
    scan_block_kernel<<<NBLK_SCAN, SCAN_B, 0, sSide>>>(cnt, rowp, bsum);
    scan_bsum_kernel<<<1, 128, 0, sSide>>>(bsum);
    scan_add_kernel<<<(NN + T - 1) / T, T, 0, sSide>>>(rowp, bsum, cursor);
    scatter_kernel<<<e8Blocks, T, 0, sSide>>>(srcE, dstE, cursor, csr_src);
    cudaEventRecord(evCSR, sSide);

    // ---- main stream: weights + CSR-independent GEMMs ----
    WtParams WP;
    WP.seg[0] = { W1,  128, 128, OFF_W1 };
    WP.seg[1] = { W2,  128, 128, OFF_W2 };
    WP.seg[2] = { W3,  128, 128, OFF_W3 };
    WP.seg[3] = { Wf,  128, 128, OFF_WF };
    WP.seg[4] = { Wh1, 448, 256, OFF_WH1 };
    WP.seg[5] = { Wh2, 256, 128, OFF_WH2 };
    WP.seg[6] = { Wh3, 128, 64,  OFF_WH3 };
    wt_build_kernel<<<(WT_TOTAL + T - 1) / T, T>>>(WP, wt);

    dim3 blk(256);
    dim3 gNode(1, (NN + 127) / 128);        // 782
    dim3 gHalfA(1, NHALF / 128);            // 391
    dim3 gHalfB(1, (NN - NHALF + 127) / 128); // 391
    dim3 gHead(1, (BB + 127) / 128);
    int aggBlkA = (NHALF + 7) / 8;          // 6256
    int aggBlkB = (NN - NHALF + 7) / 8;     // 6244

    GParams P = {};
    P.h = bufC; P.temp = temp;              // head reads h3 from bufC
    P.day_table = day_table; P.time_table = time_table; P.mode_table = mode_table;
    P.orig = origin_ids; P.dest = dest_ids;
    P.day_ids = day_ids; P.time_ids = time_ids; P.mode_ids = mode_ids;

    // temporal GEMM: fills the gap while side computes degrees
    tc_gemm_kernel<3><<<gHead, blk>>>(P, wt + OFF_WF, bf, nullptr, temp, BB, HH, HH, 1, 0);

    // GEMM1: x -> bufA (u1)
    cudaStreamWaitEvent(0, evDinv, 0);
    GParams Pa = P; Pa.A = x;
    tc_gemm_kernel<0><<<gNode, blk>>>(Pa, wt + OFF_W1, nullptr, dinv, bufA, NN, FF, HH, 2, 0);

    // join: aggregation needs the CSR
    cudaStreamWaitEvent(0, evCSR, 0);

    // --- layer 1 agg (bufA -> bufB), pipelined with GEMM2 (bufB -> bufC) ---
    agg_fused_kernel<<<aggBlkA, T>>>(rowp, csr_src, dinv, bufA, b1, bufB, 0, NHALF);
    cudaEventRecord(evA1a, 0);
    agg_fused_kernel<<<aggBlkB, T>>>(rowp, csr_src, dinv, bufA, b1, bufB, NHALF, NN);
    cudaEventRecord(evA1b, 0);

    GParams P2 = P; P2.A = bufB;
    cudaStreamWaitEvent(sSide, evA1a, 0);
    tc_gemm_kernel<1><<<gHalfA, blk, 0, sSide>>>(P2, wt + OFF_W2, nullptr, dinv, bufC,
                                                 NN, HH, HH, 2, 0);
    cudaStreamWaitEvent(sSide, evA1b, 0);
    tc_gemm_kernel<1><<<gHalfB, blk, 0, sSide>>>(P2, wt + OFF_W2, nullptr, dinv, bufC,
                                                 NN, HH, HH, 2, NHALF);
    cudaEventRecord(evG2, sSide);

    // --- layer 2 agg (bufC -> bufA), pipelined with GEMM3 (bufA -> bufB) ---
    cudaStreamWaitEvent(0, evG2, 0);
    agg_fused_kernel<<<aggBlkA, T>>>(rowp, csr_src, dinv, bufC, b2, bufA, 0, NHALF);
    cudaEventRecord(evA2a, 0);
    agg_fused_kernel<<<aggBlkB, T>>>(rowp, csr_src, dinv, bufC, b2, bufA, NHALF, NN);
    cudaEventRecord(evA2b, 0);

    GParams P3 = P; P3.A = bufA;
    cudaStreamWaitEvent(sSide, evA2a, 0);
    tc_gemm_kernel<1><<<gHalfA, blk, 0, sSide>>>(P3, wt + OFF_W3, nullptr, dinv, bufB,
                                                 NN, HH, HH, 2, 0);
    cudaStreamWaitEvent(sSide, evA2b, 0);
    tc_gemm_kernel<1><<<gHalfB, blk, 0, sSide>>>(P3, wt + OFF_W3, nullptr, dinv, bufB,
                                                 NN, HH, HH, 2, NHALF);
    cudaEventRecord(evG3, sSide);

    // --- layer 3 agg (bufB -> bufC = h3) ---
    cudaStreamWaitEvent(0, evG3, 0);
    agg_fused_kernel<<<(NN + 7) / 8, T>>>(rowp, csr_src, dinv, bufB, b3, bufC, 0, NN);

    // --- fully fused prediction head (reads bufC + temp) ---
    head_fused_kernel<<<BB / 128, blk, HF_SMEM>>>(P,
        wt + OFF_WH1, wt + OFF_WH2, wt + OFF_WH3,
        bh1, bh2, bh3, Wh4, bh4, out);
}

// round 16
// speedup vs baseline: 1.0754x; 1.0754x over previous
#include <cuda_runtime.h>
#include <cuda_bf16.h>
#include <math.h>
#include <cstdint>

// Problem constants
#define NN 100000      // nodes
#define FF 128         // node features
#define HH 128         // hidden
#define EE 1600000     // edges
#define BB 65536       // queries
#define TD 64          // H/2
#define PIN 448        // 2H + H + TD

#define SCAN_B 1024
#define NBLK_SCAN ((NN + SCAN_B - 1) / SCAN_B)   // 98

// bf16 transposed-weight pool offsets (Wt[n][k], row stride = K)
#define OFF_W1  0
#define OFF_W2  16384
#define OFF_W3  32768
#define OFF_WF  49152
#define OFF_WH1 65536          // 256 rows x 448
#define OFF_WH2 180224         // 128 rows x 256
#define OFF_WH3 212992         // 64 rows x 128
#define WT_TOTAL 221184

#define LDBYTES 144
#define ZLD1 528               // z1 row stride (256 bf16 + 16B pad)
#define ZLD2 272               // z2 row stride (128 bf16 + 16B pad)
#define HF_SMEM (2 * 128 * LDBYTES + 128 * ZLD1)   // 104448

// ---------------- scratch (static device memory; no allocation) --------------
__device__ float g_dinv[NN];
__device__ int   g_cnt  [NN];
__device__ int   g_rowp [NN + 1];
__device__ int   g_cursor[NN];
__device__ int   g_bsum [NBLK_SCAN + 1];
__device__ int   g_csr_src [EE];
__device__ __nv_bfloat16 g_wt  [WT_TOTAL];
__device__ __nv_bfloat16 g_hw  [(size_t)NN * HH];   // u = (h@W) * dinv[row]
__device__ __nv_bfloat16 g_h   [(size_t)NN * HH];
__device__ __nv_bfloat16 g_temp[(size_t)BB * HH];

// ======================= HMMA helpers ========================================
__device__ __forceinline__ uint32_t smem_to_u32(const void* p) {
    uint32_t a;
    asm("{ .reg .u64 t; cvta.to.shared.u64 t, %1; cvt.u32.u64 %0, t; }"
        : "=r"(a) : "l"(p));
    return a;
}
__device__ __forceinline__ void ldm_x4(uint32_t& r0, uint32_t& r1,
                                       uint32_t& r2, uint32_t& r3, uint32_t addr) {
    asm volatile("ldmatrix.sync.aligned.m8n8.x4.shared.b16 {%0,%1,%2,%3}, [%4];"
        : "=r"(r0), "=r"(r1), "=r"(r2), "=r"(r3) : "r"(addr));
}
__device__ __forceinline__ void mma_bf16(float* c, const uint32_t* a,
                                         uint32_t b0, uint32_t b1) {
    asm volatile(
        "mma.sync.aligned.m16n8k16.row.col.f32.bf16.bf16.f32 "
        "{%0,%1,%2,%3}, {%4,%5,%6,%7}, {%8,%9}, {%0,%1,%2,%3};"
        : "+f"(c[0]), "+f"(c[1]), "+f"(c[2]), "+f"(c[3])
        : "r"(a[0]), "r"(a[1]), "r"(a[2]), "r"(a[3]), "r"(b0), "r"(b1));
}

// ============ weight transpose + bf16 convert (once per launch) ==============
struct WtSeg { const float* src; int K; int N; int off; };
struct WtParams { WtSeg seg[7]; };

__global__ void wt_build_kernel(WtParams P, __nv_bfloat16* wt) {
    int idx = blockIdx.x * blockDim.x + threadIdx.x;
    if (idx >= WT_TOTAL) return;
    #pragma unroll
    for (int s = 0; s < 7; s++) {
        int sz = P.seg[s].K * P.seg[s].N;
        if (idx < P.seg[s].off + sz) {
            int li = idx - P.seg[s].off;
            int K = P.seg[s].K;
            int n = li / K, k = li - n * K;
            wt[idx] = __float2bfloat16(P.seg[s].src[(size_t)k * P.seg[s].N + n]);
            return;
        }
    }
}

// ======================= generic tensor-core GEMM ============================
// C[M, Ntot] = A[M, K] @ W[K, Ntot]; Wt is bf16 transposed: Wt[n][k], stride K.
// ASRC: 0 = fp32 dense, 1 = bf16 dense, 3 = tin gather
// mode 0: C = v   mode 1: C = relu(v + bias)   mode 2: C = v * dinv[row]
struct GParams {
    const void* A;
    const __nv_bfloat16* h;
    const __nv_bfloat16* temp;
    const float* day_table; const float* time_table; const float* mode_table;
    const int* orig; const int* dest; const int* day_ids; const int* time_ids;
    const int* mode_ids;
};

template<int ASRC>
__global__ void __launch_bounds__(256, 2)
tc_gemm_kernel(GParams P, const __nv_bfloat16* __restrict__ Wt,
               const float* __restrict__ bias, const float* __restrict__ dinv,
               __nv_bfloat16* __restrict__ C,
               int M, int K, int Ntot, int mode) {
    __shared__ __align__(16) char smem[2 * 128 * LDBYTES];
    char* sA = smem;
    char* sB = smem + 128 * LDBYTES;
    uint32_t sAu = smem_to_u32(sA);
    uint32_t sBu = smem_to_u32(sB);

    int tid = threadIdx.x;
    int wid = tid >> 5;
    int lane = tid & 31;
    int wm = wid >> 1;
    int wn = wid & 1;

    int rowBase = blockIdx.y * 128;
    int colBase = blockIdx.x * 128;

    float acc[2][8][4];
    #pragma unroll
    for (int mt = 0; mt < 2; mt++)
        #pragma unroll
        for (int nf = 0; nf < 8; nf++)
            #pragma unroll
            for (int j = 0; j < 4; j++) acc[mt][nf][j] = 0.0f;

    int lq = lane & 15;
    int lh = lane >> 4;

    for (int k0 = 0; k0 < K; k0 += 64) {
        __syncthreads();
        if (ASRC == 0) {
            const float* A = (const float*)P.A;
            #pragma unroll 4
            for (int i = tid; i < 128 * 32; i += 256) {
                int r = i >> 5, kp = i & 31;
                int gr = rowBase + r;
                float2 v = make_float2(0.f, 0.f);
                if (gr < M) v = *(const float2*)(A + (size_t)gr * K + k0 + 2 * kp);
                *(__nv_bfloat162*)(sA + r * LDBYTES + kp * 4) = __float22bfloat162_rn(v);
            }
        } else if (ASRC == 1) {
            const __nv_bfloat16* A = (const __nv_bfloat16*)P.A;
            #pragma unroll 4
            for (int i = tid; i < 128 * 8; i += 256) {
                int r = i >> 3, seg = i & 7;
                int gr = rowBase + r;
                uint4 v = make_uint4(0, 0, 0, 0);
                if (gr < M) v = *(const uint4*)(A + (size_t)gr * K + k0 + seg * 8);
                *(uint4*)(sA + r * LDBYTES + seg * 16) = v;
            }
        } else {
            #pragma unroll 4
            for (int i = tid; i < 128 * 32; i += 256) {
                int r = i >> 5, kp = i & 31;
                int gr = rowBase + r;
                const float* srcp = (k0 == 0)
                    ? P.day_table  + (size_t)P.day_ids[gr]  * TD
                    : P.time_table + (size_t)P.time_ids[gr] * TD;
                float2 v = *(const float2*)(srcp + 2 * kp);
                *(__nv_bfloat162*)(sA + r * LDBYTES + kp * 4) = __float22bfloat162_rn(v);
            }
        }
        #pragma unroll 4
        for (int i = tid; i < 128 * 8; i += 256) {
            int n = i >> 3, seg = i & 7;
            int gc = colBase + n;
            uint4 v = make_uint4(0, 0, 0, 0);
            if (gc < Ntot) v = *(const uint4*)(Wt + (size_t)gc * K + k0 + seg * 8);
            *(uint4*)(sB + n * LDBYTES + seg * 16) = v;
        }
        __syncthreads();

        #pragma unroll
        for (int ks = 0; ks < 4; ks++) {
            uint32_t af[2][4];
            #pragma unroll
            for (int mt = 0; mt < 2; mt++) {
                uint32_t addr = sAu + (uint32_t)(wm * 32 + mt * 16 + lq) * LDBYTES
                              + ks * 32 + lh * 16;
                ldm_x4(af[mt][0], af[mt][1], af[mt][2], af[mt][3], addr);
            }
            uint32_t bfr[8][2];
            #pragma unroll
            for (int g = 0; g < 4; g++) {
                uint32_t r0, r1, r2, r3;
                uint32_t addr = sBu + (uint32_t)(wn * 64 + g * 16 + lq) * LDBYTES
                              + ks * 32 + lh * 16;
                ldm_x4(r0, r1, r2, r3, addr);
                bfr[2 * g][0] = r0;     bfr[2 * g][1] = r2;
                bfr[2 * g + 1][0] = r1; bfr[2 * g + 1][1] = r3;
            }
            #pragma unroll
            for (int mt = 0; mt < 2; mt++)
                #pragma unroll
                for (int nf = 0; nf < 8; nf++)
                    mma_bf16(acc[mt][nf], af[mt], bfr[nf][0], bfr[nf][1]);
        }
    }

    int rowOff = lane >> 2;
    int colOff = (lane & 3) * 2;
    #pragma unroll
    for (int mt = 0; mt < 2; mt++) {
        #pragma unroll
        for (int half = 0; half < 2; half++) {
            int r = rowBase + wm * 32 + mt * 16 + rowOff + half * 8;
            if (r >= M) continue;
            float dsc = (mode == 2) ? dinv[r] : 1.0f;
            #pragma unroll
            for (int nf = 0; nf < 8; nf++) {
                int c = colBase + wn * 64 + nf * 8 + colOff;
                if (c >= Ntot) continue;
                float v0 = acc[mt][nf][half * 2 + 0];
                float v1 = acc[mt][nf][half * 2 + 1];
                if (mode == 1) {
                    v0 = fmaxf(v0 + bias[c], 0.f);
                    v1 = fmaxf(v1 + bias[c + 1], 0.f);
                } else if (mode == 2) {
                    v0 *= dsc;
                    v1 *= dsc;
                }
                *(__nv_bfloat162*)(C + (size_t)r * Ntot + c) =
                    __float22bfloat162_rn(make_float2(v0, v1));
            }
        }
    }
}

// ======================= fully fused prediction head =========================
__global__ void __launch_bounds__(256, 2)
head_fused_kernel(GParams P,
                  const __nv_bfloat16* __restrict__ WtH1,
                  const __nv_bfloat16* __restrict__ WtH2,
                  const __nv_bfloat16* __restrict__ WtH3,
                  const float* __restrict__ bh1, const float* __restrict__ bh2,
                  const float* __restrict__ bh3,
                  const float* __restrict__ w4, const float* __restrict__ b4,
                  float* __restrict__ outp) {
    extern __shared__ __align__(16) char smem[];
    char* sA = smem;
    char* sB = smem + 128 * LDBYTES;
    char* sZ = smem + 2 * 128 * LDBYTES;
    uint32_t sAu = smem_to_u32(sA);
    uint32_t sBu = smem_to_u32(sB);
    uint32_t sZu = smem_to_u32(sZ);

    int tid = threadIdx.x;
    int wid = tid >> 5;
    int lane = tid & 31;
    int wm = wid >> 1;
    int wn = wid & 1;
    int rowBase = blockIdx.x * 128;

    int lq = lane & 15;
    int lh = lane >> 4;
    int rowOff = lane >> 2;
    int colOff = (lane & 3) * 2;

    float acc[2][8][4];

    // ================= Pass 1: z1 = relu(comb @ Wh1 + bh1) ==================
    #pragma unroll 1
    for (int nh = 0; nh < 2; nh++) {
        #pragma unroll
        for (int mt = 0; mt < 2; mt++)
            #pragma unroll
            for (int nf = 0; nf < 8; nf++)
                #pragma unroll
                for (int j = 0; j < 4; j++) acc[mt][nf][j] = 0.0f;

        #pragma unroll 1
        for (int kc = 0; kc < 7; kc++) {
            int k0 = kc << 6;
            __syncthreads();
            if (k0 < 384) {
                #pragma unroll 4
                for (int i = tid; i < 128 * 8; i += 256) {
                    int r = i >> 3, seg = i & 7;
                    int gr = rowBase + r;
                    const __nv_bfloat16* srcp;
                    if (k0 < 128)       srcp = P.h + (size_t)P.orig[gr] * HH + k0;
                    else if (k0 < 256)  srcp = P.h + (size_t)P.dest[gr] * HH + (k0 - 128);
                    else                srcp = P.temp + (size_t)gr * HH + (k0 - 256);
                    *(uint4*)(sA + r * LDBYTES + seg * 16) = *(const uint4*)(srcp + seg * 8);
                }
            } else {
                #pragma unroll 4
                for (int i = tid; i < 128 * 32; i += 256) {
                    int r = i >> 5, kp = i & 31;
                    int gr = rowBase + r;
                    const float* srcp = P.mode_table + (size_t)P.mode_ids[gr] * TD;
                    float2 v = *(const float2*)(srcp + 2 * kp);
                    *(__nv_bfloat162*)(sA + r * LDBYTES + kp * 4) = __float22bfloat162_rn(v);
                }
            }
            #pragma unroll 4
            for (int i = tid; i < 128 * 8; i += 256) {
                int n = i >> 3, seg = i & 7;
                uint4 v = *(const uint4*)(WtH1 + (size_t)(nh * 128 + n) * 448 + k0 + seg * 8);
                *(uint4*)(sB + n * LDBYTES + seg * 16) = v;
            }
            __syncthreads();

            #pragma unroll
            for (int ks = 0; ks < 4; ks++) {
                uint32_t af[2][4];
                #pragma unroll
                for (int mt = 0; mt < 2; mt++) {
                    uint32_t addr = sAu + (uint32_t)(wm * 32 + mt * 16 + lq) * LDBYTES
                                  + ks * 32 + lh * 16;
                    ldm_x4(af[mt][0], af[mt][1], af[mt][2], af[mt][3], addr);
                }
                uint32_t bfr[8][2];
                #pragma unroll
                for (int g = 0; g < 4; g++) {
                    uint32_t r0, r1, r2, r3;
                    uint32_t addr = sBu + (uint32_t)(wn * 64 + g * 16 + lq) * LDBYTES
                                  + ks * 32 + lh * 16;
                    ldm_x4(r0, r1, r2, r3, addr);
                    bfr[2 * g][0] = r0;     bfr[2 * g][1] = r2;
                    bfr[2 * g + 1][0] = r1; bfr[2 * g + 1][1] = r3;
                }
                #pragma unroll
                for (int mt = 0; mt < 2; mt++)
                    #pragma unroll
                    for (int nf = 0; nf < 8; nf++)
                        mma_bf16(acc[mt][nf], af[mt], bfr[nf][0], bfr[nf][1]);
            }
        }
        #pragma unroll
        for (int mt = 0; mt < 2; mt++)
            #pragma unroll
            for (int half = 0; half < 2; half++) {
                int r = wm * 32 + mt * 16 + rowOff + half * 8;
                #pragma unroll
                for (int nf = 0; nf < 8; nf++) {
                    int c = wn * 64 + nf * 8 + colOff;
                    float v0 = fmaxf(acc[mt][nf][half * 2 + 0] + bh1[nh * 128 + c], 0.f);
                    float v1 = fmaxf(acc[mt][nf][half * 2 + 1] + bh1[nh * 128 + c + 1], 0.f);
                    *(__nv_bfloat162*)(sZ + r * ZLD1 + (nh * 128 + c) * 2) =
                        __float22bfloat162_rn(make_float2(v0, v1));
                }
            }
    }

    // ================= Pass 2: z2 = relu(z1 @ Wh2 + bh2) ====================
    #pragma unroll
    for (int mt = 0; mt < 2; mt++)
        #pragma unroll
        for (int nf = 0; nf < 8; nf++)
            #pragma unroll
            for (int j = 0; j < 4; j++) acc[mt][nf][j] = 0.0f;

    #pragma unroll 1
    for (int kc = 0; kc < 4; kc++) {
        int k0 = kc << 6;
        __syncthreads();
        #pragma unroll 4
        for (int i = tid; i < 128 * 8; i += 256) {
            int n = i >> 3, seg = i & 7;
            uint4 v = *(const uint4*)(WtH2 + (size_t)n * 256 + k0 + seg * 8);
            *(uint4*)(sB + n * LDBYTES + seg * 16) = v;
        }
        __syncthreads();

        #pragma unroll
        for (int ks = 0; ks < 4; ks++) {
            uint32_t af[2][4];
            #pragma unroll
            for (int mt = 0; mt < 2; mt++) {
                uint32_t addr = sZu + (uint32_t)(wm * 32 + mt * 16 + lq) * ZLD1
                              + kc * 128 + ks * 32 + lh * 16;
                ldm_x4(af[mt][0], af[mt][1], af[mt][2], af[mt][3], addr);
            }
            uint32_t bfr[8][2];
            #pragma unroll
            for (int g = 0; g < 4; g++) {
                uint32_t r0, r1, r2, r3;
                uint32_t addr = sBu + (uint32_t)(wn * 64 + g * 16 + lq) * LDBYTES
                              + ks * 32 + lh * 16;
                ldm_x4(r0, r1, r2, r3, addr);
                bfr[2 * g][0] = r0;     bfr[2 * g][1] = r2;
                bfr[2 * g + 1][0] = r1; bfr[2 * g + 1][1] = r3;
            }
            #pragma unroll
            for (int mt = 0; mt < 2; mt++)
                #pragma unroll
                for (int nf = 0; nf < 8; nf++)
                    mma_bf16(acc[mt][nf], af[mt], bfr[nf][0], bfr[nf][1]);
        }
    }
    __syncthreads();
    #pragma unroll
    for (int mt = 0; mt < 2; mt++)
        #pragma unroll
        for (int half = 0; half < 2; half++) {
            int r = wm * 32 + mt * 16 + rowOff + half * 8;
            #pragma unroll
            for (int nf = 0; nf < 8; nf++) {
                int c = wn * 64 + nf * 8 + colOff;
                float v0 = fmaxf(acc[mt][nf][half * 2 + 0] + bh2[c], 0.f);
                float v1 = fmaxf(acc[mt][nf][half * 2 + 1] + bh2[c + 1], 0.f);
                *(__nv_bfloat162*)(sZ + r * ZLD2 + c * 2) =
                    __float22bfloat162_rn(make_float2(v0, v1));
            }
        }

    // ============ Pass 3: z3 = relu(z2 @ Wh3 + bh3); dot Wh4; sigmoid =======
    #pragma unroll
    for (int mt = 0; mt < 2; mt++)
        #pragma unroll
        for (int nf = 0; nf < 8; nf++)
            #pragma unroll
            for (int j = 0; j < 4; j++) acc[mt][nf][j] = 0.0f;

    #pragma unroll 1
    for (int kc = 0; kc < 2; kc++) {
        int k0 = kc << 6;
        __syncthreads();
        #pragma unroll 4
        for (int i = tid; i < 128 * 8; i += 256) {
            int n = i >> 3, seg = i & 7;
            uint4 v = make_uint4(0, 0, 0, 0);
            if (n < 64) v = *(const uint4*)(WtH3 + (size_t)n * 128 + k0 + seg * 8);
            *(uint4*)(sB + n * LDBYTES + seg * 16) = v;
        }
        __syncthreads();

        #pragma unroll
        for (int ks = 0; ks < 4; ks++) {
            uint32_t af[2][4];
            #pragma unroll
            for (int mt = 0; mt < 2; mt++) {
                uint32_t addr = sZu + (uint32_t)(wm * 32 + mt * 16 + lq) * ZLD2
                              + kc * 128 + ks * 32 + lh * 16;
                ldm_x4(af[mt][0], af[mt][1], af[mt][2], af[mt][3], addr);
            }
            uint32_t bfr[8][2];
            #pragma unroll
            for (int g = 0; g < 4; g++) {
                uint32_t r0, r1, r2, r3;
                uint32_t addr = sBu + (uint32_t)(wn * 64 + g * 16 + lq) * LDBYTES
                              + ks * 32 + lh * 16;
                ldm_x4(r0, r1, r2, r3, addr);
                bfr[2 * g][0] = r0;     bfr[2 * g][1] = r2;
                bfr[2 * g + 1][0] = r1; bfr[2 * g + 1][1] = r3;
            }
            #pragma unroll
            for (int mt = 0; mt < 2; mt++)
                #pragma unroll
                for (int nf = 0; nf < 8; nf++)
                    mma_bf16(acc[mt][nf], af[mt], bfr[nf][0], bfr[nf][1]);
        }
    }

    #pragma unroll
    for (int mt = 0; mt < 2; mt++)
        #pragma unroll
        for (int half = 0; half < 2; half++) {
            int r = rowBase + wm * 32 + mt * 16 + rowOff + half * 8;
            float part = 0.0f;
            if (wn == 0) {
                #pragma unroll
                for (int nf = 0; nf < 8; nf++) {
                    int c = nf * 8 + colOff;
                    float v0 = fmaxf(acc[mt][nf][half * 2 + 0] + bh3[c], 0.f);
                    float v1 = fmaxf(acc[mt][nf][half * 2 + 1] + bh3[c + 1], 0.f);
                    part = fmaf(v0, w4[c], part);
                    part = fmaf(v1, w4[c + 1], part);
                }
            }
            part += __shfl_xor_sync(0xFFFFFFFFu, part, 1);
            part += __shfl_xor_sync(0xFFFFFFFFu, part, 2);
            if (wn == 0 && (lane & 3) == 0) {
                float v = part + b4[0];
                outp[r] = 1.0f / (1.0f + expf(-v));
            }
        }
}

// ======================= CSR build ===========================================
// 8 edges per thread for deeper MLP on the atomic chain
__global__ void cnt_count_kernel(const int* __restrict__ dst, int* cnt) {
    int i = blockIdx.x * blockDim.x + threadIdx.x;
    int e = i * 8;
    if (e + 7 < EE) {
        int4 d0 = *(const int4*)(dst + e);
        int4 d1 = *(const int4*)(dst + e + 4);
        atomicAdd(&cnt[d0.x], 1); atomicAdd(&cnt[d0.y], 1);
        atomicAdd(&cnt[d0.z], 1); atomicAdd(&cnt[d0.w], 1);
        atomicAdd(&cnt[d1.x], 1); atomicAdd(&cnt[d1.y], 1);
        atomicAdd(&cnt[d1.z], 1); atomicAdd(&cnt[d1.w], 1);
    } else {
        for (int k = e; k < EE; k++) atomicAdd(&cnt[dst[k]], 1);
    }
}
__global__ void dinv_kernel(const int* __restrict__ cnt, float* dinv) {
    int i = blockIdx.x * blockDim.x + threadIdx.x;
    if (i < NN) dinv[i] = rsqrtf((float)cnt[i] + 1.0f);
}
__global__ void scan_block_kernel(const int* __restrict__ cnt, int* excl, int* bsum) {
    __shared__ int s[SCAN_B];
    int tid = threadIdx.x;
    int i = blockIdx.x * SCAN_B + tid;
    int v = (i < NN) ? cnt[i] : 0;
    s[tid] = v;
    __syncthreads();
    for (int off = 1; off < SCAN_B; off <<= 1) {
        int t = (tid >= off) ? s[tid - off] : 0;
        __syncthreads();
        s[tid] += t;
        __syncthreads();
    }
    if (i < NN) excl[i] = s[tid] - v;
    if (tid == SCAN_B - 1) bsum[blockIdx.x] = s[tid];
}
__global__ void scan_bsum_kernel(int* bsum) {
    __shared__ int s[NBLK_SCAN];
    int tid = threadIdx.x;
    if (tid < NBLK_SCAN) s[tid] = bsum[tid];
    __syncthreads();
    if (tid == 0) {
        int run = 0;
        for (int b = 0; b < NBLK_SCAN; b++) { int t = s[b]; s[b] = run; run += t; }
    }
    __syncthreads();
    if (tid < NBLK_SCAN) bsum[tid] = s[tid];
}
__global__ void scan_add_kernel(int* rowp, const int* __restrict__ bsum, int* cursor) {
    int i = blockIdx.x * blockDim.x + threadIdx.x;
    if (i < NN) {
        int v = rowp[i] + bsum[i / SCAN_B];
        rowp[i] = v;
        cursor[i] = v;
    }
    if (i == 0) rowp[NN] = EE;
}
__global__ void scatter_kernel(const int* __restrict__ src, const int* __restrict__ dst,
                               int* cursor, int* csr_src) {
    int i = blockIdx.x * blockDim.x + threadIdx.x;
    int e = i * 8;
    if (e + 7 < EE) {
        int4 s0 = *(const int4*)(src + e);
        int4 d0 = *(const int4*)(dst + e);
        int4 s1 = *(const int4*)(src + e + 4);
        int4 d1 = *(const int4*)(dst + e + 4);
        int p0 = atomicAdd(&cursor[d0.x], 1);
        int p1 = atomicAdd(&cursor[d0.y], 1);
        int p2 = atomicAdd(&cursor[d0.z], 1);
        int p3 = atomicAdd(&cursor[d0.w], 1);
        int p4 = atomicAdd(&cursor[d1.x], 1);
        int p5 = atomicAdd(&cursor[d1.y], 1);
        int p6 = atomicAdd(&cursor[d1.z], 1);
        int p7 = atomicAdd(&cursor[d1.w], 1);
        csr_src[p0] = s0.x; csr_src[p1] = s0.y;
        csr_src[p2] = s0.z; csr_src[p3] = s0.w;
        csr_src[p4] = s1.x; csr_src[p5] = s1.y;
        csr_src[p6] = s1.z; csr_src[p7] = s1.w;
    } else {
        for (int k = e; k < EE; k++)
            csr_src[atomicAdd(&cursor[dst[k]], 1)] = src[k];
    }
}

// ====== fused aggregation: h = relu(dinv[d]*(sum_src u[src] + u[d]) + b) =====
// (exact R10/R14 form — proven fastest)
__global__ void __launch_bounds__(256)
agg_fused_kernel(const int* __restrict__ rowp,
                 const int* __restrict__ csr_src,
                 const float* __restrict__ dinv,
                 const __nv_bfloat16* __restrict__ u,
                 const float* __restrict__ bias,
                 __nv_bfloat16* __restrict__ h) {
    int node = (blockIdx.x * blockDim.x + threadIdx.x) >> 5;
    if (node >= NN) return;
    int lane = threadIdx.x & 31;
    int col = lane * 4;

    int beg = rowp[node], end = rowp[node + 1];
    float a0 = 0.f, a1 = 0.f, a2 = 0.f, a3 = 0.f;
    for (int i = beg; i < end; i += 32) {
        int n = end - i; if (n > 32) n = 32;
        int sidx = 0;
        if (lane < n) sidx = csr_src[i + lane];
        #pragma unroll 4
        for (int j = 0; j < n; j++) {
            int s = __shfl_sync(0xFFFFFFFFu, sidx, j);
            uint2 raw = *(const uint2*)(u + (size_t)s * HH + col);
            float2 f0 = __bfloat1622float2(*(__nv_bfloat162*)&raw.x);
            float2 f1 = __bfloat1622float2(*(__nv_bfloat162*)&raw.y);
            a0 += f0.x; a1 += f0.y; a2 += f1.x; a3 += f1.y;
        }
    }
    uint2 raws = *(const uint2*)(u + (size_t)node * HH + col);
    float2 fs0 = __bfloat1622float2(*(__nv_bfloat162*)&raws.x);
    float2 fs1 = __bfloat1622float2(*(__nv_bfloat162*)&raws.y);
    a0 += fs0.x; a1 += fs0.y; a2 += fs1.x; a3 += fs1.y;

    float di = dinv[node];
    const float4 b = *(const float4*)(bias + col);
    a0 = fmaxf(fmaf(a0, di, b.x), 0.f);
    a1 = fmaxf(fmaf(a1, di, b.y), 0.f);
    a2 = fmaxf(fmaf(a2, di, b.z), 0.f);
    a3 = fmaxf(fmaf(a3, di, b.w), 0.f);
    uint2 outv;
    *(__nv_bfloat162*)&outv.x = __float22bfloat162_rn(make_float2(a0, a1));
    *(__nv_bfloat162*)&outv.y = __float22bfloat162_rn(make_float2(a2, a3));
    *(uint2*)(h + (size_t)node * HH + col) = outv;
}

// =============================================================================
extern "C" void kernel_launch(void* const* d_in, const int* in_sizes, int n_in,
                              void* d_out, int out_size) {
    const float* x          = (const float*)d_in[0];
    const int*   edge_index = (const int*)  d_in[1];
    const int*   origin_ids = (const int*)  d_in[2];
    const int*   dest_ids   = (const int*)  d_in[3];
    const int*   day_ids    = (const int*)  d_in[4];
    const int*   time_ids   = (const int*)  d_in[5];
    const int*   mode_ids   = (const int*)  d_in[6];
    const float* W1 = (const float*)d_in[7];
    const float* b1 = (const float*)d_in[8];
    const float* W2 = (const float*)d_in[9];
    const float* b2 = (const float*)d_in[10];
    const float* W3 = (const float*)d_in[11];
    const float* b3 = (const float*)d_in[12];
    const float* day_table  = (const float*)d_in[13];
    const float* time_table = (const float*)d_in[14];
    const float* mode_table = (const float*)d_in[15];
    const float* Wf  = (const float*)d_in[16];
    const float* bf  = (const float*)d_in[17];
    const float* Wh1 = (const float*)d_in[18];
    const float* bh1 = (const float*)d_in[19];
    const float* Wh2 = (const float*)d_in[20];
    const float* bh2 = (const float*)d_in[21];
    const float* Wh3 = (const float*)d_in[22];
    const float* bh3 = (const float*)d_in[23];
    const float* Wh4 = (const float*)d_in[24];
    const float* bh4 = (const float*)d_in[25];
    float* out = (float*)d_out;

    const int* srcE = edge_index;
    const int* dstE = edge_index + EE;

    float* dinv;
    int *cnt, *rowp, *cursor, *bsum, *csr_src;
    __nv_bfloat16 *wt, *hw, *h, *temp;
    cudaGetSymbolAddress((void**)&dinv, g_dinv);
    cudaGetSymbolAddress((void**)&cnt,  g_cnt);
    cudaGetSymbolAddress((void**)&rowp, g_rowp);
    cudaGetSymbolAddress((void**)&cursor, g_cursor);
    cudaGetSymbolAddress((void**)&bsum, g_bsum);
    cudaGetSymbolAddress((void**)&csr_src,  g_csr_src);
    cudaGetSymbolAddress((void**)&wt,   g_wt);
    cudaGetSymbolAddress((void**)&hw,   g_hw);
    cudaGetSymbolAddress((void**)&h,    g_h);
    cudaGetSymbolAddress((void**)&temp, g_temp);

    // --- side stream + events + attributes (created once) ---
    static cudaStream_t sSide = nullptr;
    static cudaEvent_t evRoot = nullptr, evDinv = nullptr, evCSR = nullptr;
    if (!sSide) {
        cudaStreamCreateWithFlags(&sSide, cudaStreamNonBlocking);
        cudaEventCreateWithFlags(&evRoot, cudaEventDisableTiming);
        cudaEventCreateWithFlags(&evDinv, cudaEventDisableTiming);
        cudaEventCreateWithFlags(&evCSR,  cudaEventDisableTiming);
        cudaFuncSetAttribute(head_fused_kernel,
            cudaFuncAttributeMaxDynamicSharedMemorySize, HF_SMEM);
    }

    const int T = 256;
    int e8Blocks = (int)(((size_t)(EE + 7) / 8 + T - 1) / T);

    // ---- fork: CSR build on side stream ----
    cudaEventRecord(evRoot, 0);
    cudaStreamWaitEvent(sSide, evRoot, 0);
    cudaMemsetAsync(cnt, 0, NN * sizeof(int), sSide);
    cnt_count_kernel<<<e8Blocks, T, 0, sSide>>>(dstE, cnt);
    dinv_kernel<<<(NN + T - 1) / T, T, 0, sSide>>>(cnt, dinv);
    cudaEventRecord(evDinv, sSide);
    scan_block_kernel<<<NBLK_SCAN, SCAN_B, 0, sSide>>>(cnt, rowp, bsum);
    scan_bsum_kernel<<<1, 128, 0, sSide>>>(bsum);
    scan_add_kernel<<<(NN + T - 1) / T, T, 0, sSide>>>(rowp, bsum, cursor);
    scatter_kernel<<<e8Blocks, T, 0, sSide>>>(srcE, dstE, cursor, csr_src);
    cudaEventRecord(evCSR, sSide);

    // ---- main stream: weights + CSR-independent GEMMs ----
    WtParams WP;
    WP.seg[0] = { W1,  128, 128, OFF_W1 };
    WP.seg[1] = { W2,  128, 128, OFF_W2 };
    WP.seg[2] = { W3,  128, 128, OFF_W3 };
    WP.seg[3] = { Wf,  128, 128, OFF_WF };
    WP.seg[4] = { Wh1, 448, 256, OFF_WH1 };
    WP.seg[5] = { Wh2, 256, 128, OFF_WH2 };
    WP.seg[6] = { Wh3, 128, 64,  OFF_WH3 };
    wt_build_kernel<<<(WT_TOTAL + T - 1) / T, T>>>(WP, wt);

    dim3 blk(256);
    dim3 gNode(1, (NN + 127) / 128);
    dim3 gHead(1, (BB + 127) / 128);
    int aggBlocks = (NN + 7) / 8;

    GParams P = {};
    P.h = h; P.temp = temp;
    P.day_table = day_table; P.time_table = time_table; P.mode_table = mode_table;
    P.orig = origin_ids; P.dest = dest_ids;
    P.day_ids = day_ids; P.time_ids = time_ids; P.mode_ids = mode_ids;

    // temporal GEMM: fills the gap while side computes degrees
    tc_gemm_kernel<3><<<gHead, blk>>>(P, wt + OFF_WF, bf, nullptr, temp, BB, HH, HH, 1);

    // GEMM1 needs dinv only
    cudaStreamWaitEvent(0, evDinv, 0);
    GParams Pa = P; Pa.A = x;
    tc_gemm_kernel<0><<<gNode, blk>>>(Pa, wt + OFF_W1, nullptr, dinv, hw, NN, FF, HH, 2);

    // join: aggregation needs the CSR
    cudaStreamWaitEvent(0, evCSR, 0);

    // --- GCN layers ---
    agg_fused_kernel<<<aggBlocks, T>>>(rowp, csr_src, dinv, hw, b1, h);
    Pa.A = h;
    tc_gemm_kernel<1><<<gNode, blk>>>(Pa, wt + OFF_W2, nullptr, dinv, hw, NN, HH, HH, 2);
    agg_fused_kernel<<<aggBlocks, T>>>(rowp, csr_src, dinv, hw, b2, h);
    tc_gemm_kernel<1><<<gNode, blk>>>(Pa, wt + OFF_W3, nullptr, dinv, hw, NN, HH, HH, 2);
    agg_fused_kernel<<<aggBlocks, T>>>(rowp, csr_src, dinv, hw, b3, h);

    // --- fully fused prediction head ---
    head_fused_kernel<<<BB / 128, blk, HF_SMEM>>>(P,
        wt + OFF_WH1, wt + OFF_WH2, wt + OFF_WH3,
        bh1, bh2, bh3, Wh4, bh4, out);
}

// round 17
// speedup vs baseline: 1.1061x; 1.0285x over previous
#include <cuda_runtime.h>
#include <cuda_bf16.h>
#include <math.h>
#include <cstdint>

// Problem constants
#define NN 100000      // nodes
#define FF 128         // node features
#define HH 128         // hidden
#define EE 1600000     // edges
#define BB 65536       // queries
#define TD 64          // H/2
#define PIN 448        // 2H + H + TD

#define SCAN_B 1024
#define NBLK_SCAN ((NN + SCAN_B - 1) / SCAN_B)   // 98

// bf16 transposed-weight pool offsets (Wt[n][k], row stride = K)
#define OFF_W1  0
#define OFF_W2  16384
#define OFF_W3  32768
#define OFF_WF  49152
#define OFF_WH1 65536          // 256 rows x 448
#define OFF_WH2 180224         // 128 rows x 256
#define OFF_WH3 212992         // 64 rows x 128
#define WT_TOTAL 221184

#define LDBYTES 144
#define ZLD1 528               // z1 row stride (256 bf16 + 16B pad)
#define ZLD2 272               // z2 row stride (128 bf16 + 16B pad)
#define HF_SMEM (2 * 128 * LDBYTES + 128 * ZLD1)   // 104448

// ---------------- scratch (static device memory; no allocation) --------------
__device__ float g_dinv[NN];
__device__ int   g_cnt  [NN];
__device__ int   g_rowp [NN + 1];
__device__ int   g_cursor[NN];
__device__ int   g_bsum [NBLK_SCAN + 1];
__device__ int   g_csr_src [EE];
__device__ __nv_bfloat16 g_wt  [WT_TOTAL];
__device__ __nv_bfloat16 g_hw  [(size_t)NN * HH];   // u = (h@W) * dinv[row]
__device__ __nv_bfloat16 g_h   [(size_t)NN * HH];
__device__ __nv_bfloat16 g_temp[(size_t)BB * HH];

// ======================= HMMA helpers ========================================
__device__ __forceinline__ uint32_t smem_to_u32(const void* p) {
    uint32_t a;
    asm("{ .reg .u64 t; cvta.to.shared.u64 t, %1; cvt.u32.u64 %0, t; }"
        : "=r"(a) : "l"(p));
    return a;
}
__device__ __forceinline__ void ldm_x4(uint32_t& r0, uint32_t& r1,
                                       uint32_t& r2, uint32_t& r3, uint32_t addr) {
    asm volatile("ldmatrix.sync.aligned.m8n8.x4.shared.b16 {%0,%1,%2,%3}, [%4];"
        : "=r"(r0), "=r"(r1), "=r"(r2), "=r"(r3) : "r"(addr));
}
__device__ __forceinline__ void mma_bf16(float* c, const uint32_t* a,
                                         uint32_t b0, uint32_t b1) {
    asm volatile(
        "mma.sync.aligned.m16n8k16.row.col.f32.bf16.bf16.f32 "
        "{%0,%1,%2,%3}, {%4,%5,%6,%7}, {%8,%9}, {%0,%1,%2,%3};"
        : "+f"(c[0]), "+f"(c[1]), "+f"(c[2]), "+f"(c[3])
        : "r"(a[0]), "r"(a[1]), "r"(a[2]), "r"(a[3]), "r"(b0), "r"(b1));
}

// ============ weight transpose + bf16 convert (once per launch) ==============
struct WtSeg { const float* src; int K; int N; int off; };
struct WtParams { WtSeg seg[7]; };

__global__ void wt_build_kernel(WtParams P, __nv_bfloat16* wt) {
    int idx = blockIdx.x * blockDim.x + threadIdx.x;
    if (idx >= WT_TOTAL) return;
    #pragma unroll
    for (int s = 0; s < 7; s++) {
        int sz = P.seg[s].K * P.seg[s].N;
        if (idx < P.seg[s].off + sz) {
            int li = idx - P.seg[s].off;
            int K = P.seg[s].K;
            int n = li / K, k = li - n * K;
            wt[idx] = __float2bfloat16(P.seg[s].src[(size_t)k * P.seg[s].N + n]);
            return;
        }
    }
}

// ======================= generic tensor-core GEMM ============================
// C[M, Ntot] = A[M, K] @ W[K, Ntot]; Wt is bf16 transposed: Wt[n][k], stride K.
// ASRC: 0 = fp32 dense, 1 = bf16 dense, 3 = tin gather
// mode 0: C = v   mode 1: C = relu(v + bias)   mode 2: C = v * dinv[row]
struct GParams {
    const void* A;
    const __nv_bfloat16* h;
    const __nv_bfloat16* temp;
    const float* day_table; const float* time_table; const float* mode_table;
    const int* orig; const int* dest; const int* day_ids; const int* time_ids;
    const int* mode_ids;
};

template<int ASRC>
__global__ void __launch_bounds__(256, 2)
tc_gemm_kernel(GParams P, const __nv_bfloat16* __restrict__ Wt,
               const float* __restrict__ bias, const float* __restrict__ dinv,
               __nv_bfloat16* __restrict__ C,
               int M, int K, int Ntot, int mode) {
    __shared__ __align__(16) char smem[2 * 128 * LDBYTES];
    char* sA = smem;
    char* sB = smem + 128 * LDBYTES;
    uint32_t sAu = smem_to_u32(sA);
    uint32_t sBu = smem_to_u32(sB);

    int tid = threadIdx.x;
    int wid = tid >> 5;
    int lane = tid & 31;
    int wm = wid >> 1;
    int wn = wid & 1;

    int rowBase = blockIdx.y * 128;
    int colBase = blockIdx.x * 128;

    float acc[2][8][4];
    #pragma unroll
    for (int mt = 0; mt < 2; mt++)
        #pragma unroll
        for (int nf = 0; nf < 8; nf++)
            #pragma unroll
            for (int j = 0; j < 4; j++) acc[mt][nf][j] = 0.0f;

    int lq = lane & 15;
    int lh = lane >> 4;

    for (int k0 = 0; k0 < K; k0 += 64) {
        __syncthreads();
        if (ASRC == 0) {
            const float* A = (const float*)P.A;
            #pragma unroll 4
            for (int i = tid; i < 128 * 32; i += 256) {
                int r = i >> 5, kp = i & 31;
                int gr = rowBase + r;
                float2 v = make_float2(0.f, 0.f);
                if (gr < M) v = *(const float2*)(A + (size_t)gr * K + k0 + 2 * kp);
                *(__nv_bfloat162*)(sA + r * LDBYTES + kp * 4) = __float22bfloat162_rn(v);
            }
        } else if (ASRC == 1) {
            const __nv_bfloat16* A = (const __nv_bfloat16*)P.A;
            #pragma unroll 4
            for (int i = tid; i < 128 * 8; i += 256) {
                int r = i >> 3, seg = i & 7;
                int gr = rowBase + r;
                uint4 v = make_uint4(0, 0, 0, 0);
                if (gr < M) v = *(const uint4*)(A + (size_t)gr * K + k0 + seg * 8);
                *(uint4*)(sA + r * LDBYTES + seg * 16) = v;
            }
        } else {
            #pragma unroll 4
            for (int i = tid; i < 128 * 32; i += 256) {
                int r = i >> 5, kp = i & 31;
                int gr = rowBase + r;
                const float* srcp = (k0 == 0)
                    ? P.day_table  + (size_t)P.day_ids[gr]  * TD
                    : P.time_table + (size_t)P.time_ids[gr] * TD;
                float2 v = *(const float2*)(srcp + 2 * kp);
                *(__nv_bfloat162*)(sA + r * LDBYTES + kp * 4) = __float22bfloat162_rn(v);
            }
        }
        #pragma unroll 4
        for (int i = tid; i < 128 * 8; i += 256) {
            int n = i >> 3, seg = i & 7;
            int gc = colBase + n;
            uint4 v = make_uint4(0, 0, 0, 0);
            if (gc < Ntot) v = *(const uint4*)(Wt + (size_t)gc * K + k0 + seg * 8);
            *(uint4*)(sB + n * LDBYTES + seg * 16) = v;
        }
        __syncthreads();

        #pragma unroll
        for (int ks = 0; ks < 4; ks++) {
            uint32_t af[2][4];
            #pragma unroll
            for (int mt = 0; mt < 2; mt++) {
                uint32_t addr = sAu + (uint32_t)(wm * 32 + mt * 16 + lq) * LDBYTES
                              + ks * 32 + lh * 16;
                ldm_x4(af[mt][0], af[mt][1], af[mt][2], af[mt][3], addr);
            }
            uint32_t bfr[8][2];
            #pragma unroll
            for (int g = 0; g < 4; g++) {
                uint32_t r0, r1, r2, r3;
                uint32_t addr = sBu + (uint32_t)(wn * 64 + g * 16 + lq) * LDBYTES
                              + ks * 32 + lh * 16;
                ldm_x4(r0, r1, r2, r3, addr);
                bfr[2 * g][0] = r0;     bfr[2 * g][1] = r2;
                bfr[2 * g + 1][0] = r1; bfr[2 * g + 1][1] = r3;
            }
            #pragma unroll
            for (int mt = 0; mt < 2; mt++)
                #pragma unroll
                for (int nf = 0; nf < 8; nf++)
                    mma_bf16(acc[mt][nf], af[mt], bfr[nf][0], bfr[nf][1]);
        }
    }

    int rowOff = lane >> 2;
    int colOff = (lane & 3) * 2;
    #pragma unroll
    for (int mt = 0; mt < 2; mt++) {
        #pragma unroll
        for (int half = 0; half < 2; half++) {
            int r = rowBase + wm * 32 + mt * 16 + rowOff + half * 8;
            if (r >= M) continue;
            float dsc = (mode == 2) ? dinv[r] : 1.0f;
            #pragma unroll
            for (int nf = 0; nf < 8; nf++) {
                int c = colBase + wn * 64 + nf * 8 + colOff;
                if (c >= Ntot) continue;
                float v0 = acc[mt][nf][half * 2 + 0];
                float v1 = acc[mt][nf][half * 2 + 1];
                if (mode == 1) {
                    v0 = fmaxf(v0 + bias[c], 0.f);
                    v1 = fmaxf(v1 + bias[c + 1], 0.f);
                } else if (mode == 2) {
                    v0 *= dsc;
                    v1 *= dsc;
                }
                *(__nv_bfloat162*)(C + (size_t)r * Ntot + c) =
                    __float22bfloat162_rn(make_float2(v0, v1));
            }
        }
    }
}

// ======================= fully fused prediction head =========================
__global__ void __launch_bounds__(256, 2)
head_fused_kernel(GParams P,
                  const __nv_bfloat16* __restrict__ WtH1,
                  const __nv_bfloat16* __restrict__ WtH2,
                  const __nv_bfloat16* __restrict__ WtH3,
                  const float* __restrict__ bh1, const float* __restrict__ bh2,
                  const float* __restrict__ bh3,
                  const float* __restrict__ w4, const float* __restrict__ b4,
                  float* __restrict__ outp) {
    extern __shared__ __align__(16) char smem[];
    char* sA = smem;
    char* sB = smem + 128 * LDBYTES;
    char* sZ = smem + 2 * 128 * LDBYTES;
    uint32_t sAu = smem_to_u32(sA);
    uint32_t sBu = smem_to_u32(sB);
    uint32_t sZu = smem_to_u32(sZ);

    int tid = threadIdx.x;
    int wid = tid >> 5;
    int lane = tid & 31;
    int wm = wid >> 1;
    int wn = wid & 1;
    int rowBase = blockIdx.x * 128;

    int lq = lane & 15;
    int lh = lane >> 4;
    int rowOff = lane >> 2;
    int colOff = (lane & 3) * 2;

    float acc[2][8][4];

    // ================= Pass 1: z1 = relu(comb @ Wh1 + bh1) ==================
    #pragma unroll 1
    for (int nh = 0; nh < 2; nh++) {
        #pragma unroll
        for (int mt = 0; mt < 2; mt++)
            #pragma unroll
            for (int nf = 0; nf < 8; nf++)
                #pragma unroll
                for (int j = 0; j < 4; j++) acc[mt][nf][j] = 0.0f;

        #pragma unroll 1
        for (int kc = 0; kc < 7; kc++) {
            int k0 = kc << 6;
            __syncthreads();
            if (k0 < 384) {
                #pragma unroll 4
                for (int i = tid; i < 128 * 8; i += 256) {
                    int r = i >> 3, seg = i & 7;
                    int gr = rowBase + r;
                    const __nv_bfloat16* srcp;
                    if (k0 < 128)       srcp = P.h + (size_t)P.orig[gr] * HH + k0;
                    else if (k0 < 256)  srcp = P.h + (size_t)P.dest[gr] * HH + (k0 - 128);
                    else                srcp = P.temp + (size_t)gr * HH + (k0 - 256);
                    *(uint4*)(sA + r * LDBYTES + seg * 16) = *(const uint4*)(srcp + seg * 8);
                }
            } else {
                #pragma unroll 4
                for (int i = tid; i < 128 * 32; i += 256) {
                    int r = i >> 5, kp = i & 31;
                    int gr = rowBase + r;
                    const float* srcp = P.mode_table + (size_t)P.mode_ids[gr] * TD;
                    float2 v = *(const float2*)(srcp + 2 * kp);
                    *(__nv_bfloat162*)(sA + r * LDBYTES + kp * 4) = __float22bfloat162_rn(v);
                }
            }
            #pragma unroll 4
            for (int i = tid; i < 128 * 8; i += 256) {
                int n = i >> 3, seg = i & 7;
                uint4 v = *(const uint4*)(WtH1 + (size_t)(nh * 128 + n) * 448 + k0 + seg * 8);
                *(uint4*)(sB + n * LDBYTES + seg * 16) = v;
            }
            __syncthreads();

            #pragma unroll
            for (int ks = 0; ks < 4; ks++) {
                uint32_t af[2][4];
                #pragma unroll
                for (int mt = 0; mt < 2; mt++) {
                    uint32_t addr = sAu + (uint32_t)(wm * 32 + mt * 16 + lq) * LDBYTES
                                  + ks * 32 + lh * 16;
                    ldm_x4(af[mt][0], af[mt][1], af[mt][2], af[mt][3], addr);
                }
                uint32_t bfr[8][2];
                #pragma unroll
                for (int g = 0; g < 4; g++) {
                    uint32_t r0, r1, r2, r3;
                    uint32_t addr = sBu + (uint32_t)(wn * 64 + g * 16 + lq) * LDBYTES
                                  + ks * 32 + lh * 16;
                    ldm_x4(r0, r1, r2, r3, addr);
                    bfr[2 * g][0] = r0;     bfr[2 * g][1] = r2;
                    bfr[2 * g + 1][0] = r1; bfr[2 * g + 1][1] = r3;
                }
                #pragma unroll
                for (int mt = 0; mt < 2; mt++)
                    #pragma unroll
                    for (int nf = 0; nf < 8; nf++)
                        mma_bf16(acc[mt][nf], af[mt], bfr[nf][0], bfr[nf][1]);
            }
        }
        #pragma unroll
        for (int mt = 0; mt < 2; mt++)
            #pragma unroll
            for (int half = 0; half < 2; half++) {
                int r = wm * 32 + mt * 16 + rowOff + half * 8;
                #pragma unroll
                for (int nf = 0; nf < 8; nf++) {
                    int c = wn * 64 + nf * 8 + colOff;
                    float v0 = fmaxf(acc[mt][nf][half * 2 + 0] + bh1[nh * 128 + c], 0.f);
                    float v1 = fmaxf(acc[mt][nf][half * 2 + 1] + bh1[nh * 128 + c + 1], 0.f);
                    *(__nv_bfloat162*)(sZ + r * ZLD1 + (nh * 128 + c) * 2) =
                        __float22bfloat162_rn(make_float2(v0, v1));
                }
            }
    }

    // ================= Pass 2: z2 = relu(z1 @ Wh2 + bh2) ====================
    #pragma unroll
    for (int mt = 0; mt < 2; mt++)
        #pragma unroll
        for (int nf = 0; nf < 8; nf++)
            #pragma unroll
            for (int j = 0; j < 4; j++) acc[mt][nf][j] = 0.0f;

    #pragma unroll 1
    for (int kc = 0; kc < 4; kc++) {
        int k0 = kc << 6;
        __syncthreads();
        #pragma unroll 4
        for (int i = tid; i < 128 * 8; i += 256) {
            int n = i >> 3, seg = i & 7;
            uint4 v = *(const uint4*)(WtH2 + (size_t)n * 256 + k0 + seg * 8);
            *(uint4*)(sB + n * LDBYTES + seg * 16) = v;
        }
        __syncthreads();

        #pragma unroll
        for (int ks = 0; ks < 4; ks++) {
            uint32_t af[2][4];
            #pragma unroll
            for (int mt = 0; mt < 2; mt++) {
                uint32_t addr = sZu + (uint32_t)(wm * 32 + mt * 16 + lq) * ZLD1
                              + kc * 128 + ks * 32 + lh * 16;
                ldm_x4(af[mt][0], af[mt][1], af[mt][2], af[mt][3], addr);
            }
            uint32_t bfr[8][2];
            #pragma unroll
            for (int g = 0; g < 4; g++) {
                uint32_t r0, r1, r2, r3;
                uint32_t addr = sBu + (uint32_t)(wn * 64 + g * 16 + lq) * LDBYTES
                              + ks * 32 + lh * 16;
                ldm_x4(r0, r1, r2, r3, addr);
                bfr[2 * g][0] = r0;     bfr[2 * g][1] = r2;
                bfr[2 * g + 1][0] = r1; bfr[2 * g + 1][1] = r3;
            }
            #pragma unroll
            for (int mt = 0; mt < 2; mt++)
                #pragma unroll
                for (int nf = 0; nf < 8; nf++)
                    mma_bf16(acc[mt][nf], af[mt], bfr[nf][0], bfr[nf][1]);
        }
    }
    __syncthreads();
    #pragma unroll
    for (int mt = 0; mt < 2; mt++)
        #pragma unroll
        for (int half = 0; half < 2; half++) {
            int r = wm * 32 + mt * 16 + rowOff + half * 8;
            #pragma unroll
            for (int nf = 0; nf < 8; nf++) {
                int c = wn * 64 + nf * 8 + colOff;
                float v0 = fmaxf(acc[mt][nf][half * 2 + 0] + bh2[c], 0.f);
                float v1 = fmaxf(acc[mt][nf][half * 2 + 1] + bh2[c + 1], 0.f);
                *(__nv_bfloat162*)(sZ + r * ZLD2 + c * 2) =
                    __float22bfloat162_rn(make_float2(v0, v1));
            }
        }

    // ============ Pass 3: z3 = relu(z2 @ Wh3 + bh3); dot Wh4; sigmoid =======
    #pragma unroll
    for (int mt = 0; mt < 2; mt++)
        #pragma unroll
        for (int nf = 0; nf < 8; nf++)
            #pragma unroll
            for (int j = 0; j < 4; j++) acc[mt][nf][j] = 0.0f;

    #pragma unroll 1
    for (int kc = 0; kc < 2; kc++) {
        int k0 = kc << 6;
        __syncthreads();
        #pragma unroll 4
        for (int i = tid; i < 128 * 8; i += 256) {
            int n = i >> 3, seg = i & 7;
            uint4 v = make_uint4(0, 0, 0, 0);
            if (n < 64) v = *(const uint4*)(WtH3 + (size_t)n * 128 + k0 + seg * 8);
            *(uint4*)(sB + n * LDBYTES + seg * 16) = v;
        }
        __syncthreads();

        #pragma unroll
        for (int ks = 0; ks < 4; ks++) {
            uint32_t af[2][4];
            #pragma unroll
            for (int mt = 0; mt < 2; mt++) {
                uint32_t addr = sZu + (uint32_t)(wm * 32 + mt * 16 + lq) * ZLD2
                              + kc * 128 + ks * 32 + lh * 16;
                ldm_x4(af[mt][0], af[mt][1], af[mt][2], af[mt][3], addr);
            }
            uint32_t bfr[8][2];
            #pragma unroll
            for (int g = 0; g < 4; g++) {
                uint32_t r0, r1, r2, r3;
                uint32_t addr = sBu + (uint32_t)(wn * 64 + g * 16 + lq) * LDBYTES
                              + ks * 32 + lh * 16;
                ldm_x4(r0, r1, r2, r3, addr);
                bfr[2 * g][0] = r0;     bfr[2 * g][1] = r2;
                bfr[2 * g + 1][0] = r1; bfr[2 * g + 1][1] = r3;
            }
            #pragma unroll
            for (int mt = 0; mt < 2; mt++)
                #pragma unroll
                for (int nf = 0; nf < 8; nf++)
                    mma_bf16(acc[mt][nf], af[mt], bfr[nf][0], bfr[nf][1]);
        }
    }

    #pragma unroll
    for (int mt = 0; mt < 2; mt++)
        #pragma unroll
        for (int half = 0; half < 2; half++) {
            int r = rowBase + wm * 32 + mt * 16 + rowOff + half * 8;
            float part = 0.0f;
            if (wn == 0) {
                #pragma unroll
                for (int nf = 0; nf < 8; nf++) {
                    int c = nf * 8 + colOff;
                    float v0 = fmaxf(acc[mt][nf][half * 2 + 0] + bh3[c], 0.f);
                    float v1 = fmaxf(acc[mt][nf][half * 2 + 1] + bh3[c + 1], 0.f);
                    part = fmaf(v0, w4[c], part);
                    part = fmaf(v1, w4[c + 1], part);
                }
            }
            part += __shfl_xor_sync(0xFFFFFFFFu, part, 1);
            part += __shfl_xor_sync(0xFFFFFFFFu, part, 2);
            if (wn == 0 && (lane & 3) == 0) {
                float v = part + b4[0];
                outp[r] = 1.0f / (1.0f + expf(-v));
            }
        }
}

// ======================= CSR build ===========================================
__global__ void cnt_count_kernel(const int* __restrict__ dst, int* cnt) {
    int i = blockIdx.x * blockDim.x + threadIdx.x;
    int e = i * 8;
    if (e + 7 < EE) {
        int4 d0 = *(const int4*)(dst + e);
        int4 d1 = *(const int4*)(dst + e + 4);
        atomicAdd(&cnt[d0.x], 1); atomicAdd(&cnt[d0.y], 1);
        atomicAdd(&cnt[d0.z], 1); atomicAdd(&cnt[d0.w], 1);
        atomicAdd(&cnt[d1.x], 1); atomicAdd(&cnt[d1.y], 1);
        atomicAdd(&cnt[d1.z], 1); atomicAdd(&cnt[d1.w], 1);
    } else {
        for (int k = e; k < EE; k++) atomicAdd(&cnt[dst[k]], 1);
    }
}
__global__ void dinv_kernel(const int* __restrict__ cnt, float* dinv) {
    int i = blockIdx.x * blockDim.x + threadIdx.x;
    if (i < NN) dinv[i] = rsqrtf((float)cnt[i] + 1.0f);
}
__global__ void scan_block_kernel(const int* __restrict__ cnt, int* excl, int* bsum) {
    __shared__ int s[SCAN_B];
    int tid = threadIdx.x;
    int i = blockIdx.x * SCAN_B + tid;
    int v = (i < NN) ? cnt[i] : 0;
    s[tid] = v;
    __syncthreads();
    for (int off = 1; off < SCAN_B; off <<= 1) {
        int t = (tid >= off) ? s[tid - off] : 0;
        __syncthreads();
        s[tid] += t;
        __syncthreads();
    }
    if (i < NN) excl[i] = s[tid] - v;
    if (tid == SCAN_B - 1) bsum[blockIdx.x] = s[tid];
}
__global__ void scan_bsum_kernel(int* bsum) {
    __shared__ int s[NBLK_SCAN];
    int tid = threadIdx.x;
    if (tid < NBLK_SCAN) s[tid] = bsum[tid];
    __syncthreads();
    if (tid == 0) {
        int run = 0;
        for (int b = 0; b < NBLK_SCAN; b++) { int t = s[b]; s[b] = run; run += t; }
    }
    __syncthreads();
    if (tid < NBLK_SCAN) bsum[tid] = s[tid];
}
__global__ void scan_add_kernel(int* rowp, const int* __restrict__ bsum, int* cursor) {
    int i = blockIdx.x * blockDim.x + threadIdx.x;
    if (i < NN) {
        int v = rowp[i] + bsum[i / SCAN_B];
        rowp[i] = v;
        cursor[i] = v;
    }
    if (i == 0) rowp[NN] = EE;
}
__global__ void scatter_kernel(const int* __restrict__ src, const int* __restrict__ dst,
                               int* cursor, int* csr_src) {
    int i = blockIdx.x * blockDim.x + threadIdx.x;
    int e = i * 8;
    if (e + 7 < EE) {
        int4 s0 = *(const int4*)(src + e);
        int4 d0 = *(const int4*)(dst + e);
        int4 s1 = *(const int4*)(src + e + 4);
        int4 d1 = *(const int4*)(dst + e + 4);
        int p0 = atomicAdd(&cursor[d0.x], 1);
        int p1 = atomicAdd(&cursor[d0.y], 1);
        int p2 = atomicAdd(&cursor[d0.z], 1);
        int p3 = atomicAdd(&cursor[d0.w], 1);
        int p4 = atomicAdd(&cursor[d1.x], 1);
        int p5 = atomicAdd(&cursor[d1.y], 1);
        int p6 = atomicAdd(&cursor[d1.z], 1);
        int p7 = atomicAdd(&cursor[d1.w], 1);
        csr_src[p0] = s0.x; csr_src[p1] = s0.y;
        csr_src[p2] = s0.z; csr_src[p3] = s0.w;
        csr_src[p4] = s1.x; csr_src[p5] = s1.y;
        csr_src[p6] = s1.z; csr_src[p7] = s1.w;
    } else {
        for (int k = e; k < EE; k++)
            csr_src[atomicAdd(&cursor[dst[k]], 1)] = src[k];
    }
}

// ====== fused aggregation: h = relu(dinv[d]*(sum_src u[src] + u[d]) + b) =====
// bf16x2 HADD2 accumulation: inner loop = 1 LDG.64 + 2 HADD2 per edge
__global__ void __launch_bounds__(256)
agg_fused_kernel(const int* __restrict__ rowp,
                 const int* __restrict__ csr_src,
                 const float* __restrict__ dinv,
                 const __nv_bfloat16* __restrict__ u,
                 const float* __restrict__ bias,
                 __nv_bfloat16* __restrict__ h) {
    int node = (blockIdx.x * blockDim.x + threadIdx.x) >> 5;
    if (node >= NN) return;
    int lane = threadIdx.x & 31;
    int col = lane * 4;

    int beg = rowp[node], end = rowp[node + 1];
    __nv_bfloat162 s01 = __float2bfloat162_rn(0.f);
    __nv_bfloat162 s23 = __float2bfloat162_rn(0.f);
    for (int i = beg; i < end; i += 32) {
        int n = end - i; if (n > 32) n = 32;
        int sidx = 0;
        if (lane < n) sidx = csr_src[i + lane];
        #pragma unroll 4
        for (int j = 0; j < n; j++) {
            int s = __shfl_sync(0xFFFFFFFFu, sidx, j);
            uint2 raw = *(const uint2*)(u + (size_t)s * HH + col);
            s01 = __hadd2(s01, *(__nv_bfloat162*)&raw.x);
            s23 = __hadd2(s23, *(__nv_bfloat162*)&raw.y);
        }
    }
    float2 f01 = __bfloat1622float2(s01);
    float2 f23 = __bfloat1622float2(s23);
    float a0 = f01.x, a1 = f01.y, a2 = f23.x, a3 = f23.y;

    uint2 raws = *(const uint2*)(u + (size_t)node * HH + col);
    float2 fs0 = __bfloat1622float2(*(__nv_bfloat162*)&raws.x);
    float2 fs1 = __bfloat1622float2(*(__nv_bfloat162*)&raws.y);
    a0 += fs0.x; a1 += fs0.y; a2 += fs1.x; a3 += fs1.y;

    float di = dinv[node];
    const float4 b = *(const float4*)(bias + col);
    a0 = fmaxf(fmaf(a0, di, b.x), 0.f);
    a1 = fmaxf(fmaf(a1, di, b.y), 0.f);
    a2 = fmaxf(fmaf(a2, di, b.z), 0.f);
    a3 = fmaxf(fmaf(a3, di, b.w), 0.f);
    uint2 outv;
    *(__nv_bfloat162*)&outv.x = __float22bfloat162_rn(make_float2(a0, a1));
    *(__nv_bfloat162*)&outv.y = __float22bfloat162_rn(make_float2(a2, a3));
    *(uint2*)(h + (size_t)node * HH + col) = outv;
}

// =============================================================================
extern "C" void kernel_launch(void* const* d_in, const int* in_sizes, int n_in,
                              void* d_out, int out_size) {
    const float* x          = (const float*)d_in[0];
    const int*   edge_index = (const int*)  d_in[1];
    const int*   origin_ids = (const int*)  d_in[2];
    const int*   dest_ids   = (const int*)  d_in[3];
    const int*   day_ids    = (const int*)  d_in[4];
    const int*   time_ids   = (const int*)  d_in[5];
    const int*   mode_ids   = (const int*)  d_in[6];
    const float* W1 = (const float*)d_in[7];
    const float* b1 = (const float*)d_in[8];
    const float* W2 = (const float*)d_in[9];
    const float* b2 = (const float*)d_in[10];
    const float* W3 = (const float*)d_in[11];
    const float* b3 = (const float*)d_in[12];
    const float* day_table  = (const float*)d_in[13];
    const float* time_table = (const float*)d_in[14];
    const float* mode_table = (const float*)d_in[15];
    const float* Wf  = (const float*)d_in[16];
    const float* bf  = (const float*)d_in[17];
    const float* Wh1 = (const float*)d_in[18];
    const float* bh1 = (const float*)d_in[19];
    const float* Wh2 = (const float*)d_in[20];
    const float* bh2 = (const float*)d_in[21];
    const float* Wh3 = (const float*)d_in[22];
    const float* bh3 = (const float*)d_in[23];
    const float* Wh4 = (const float*)d_in[24];
    const float* bh4 = (const float*)d_in[25];
    float* out = (float*)d_out;

    const int* srcE = edge_index;
    const int* dstE = edge_index + EE;

    float* dinv;
    int *cnt, *rowp, *cursor, *bsum, *csr_src;
    __nv_bfloat16 *wt, *hw, *h, *temp;
    cudaGetSymbolAddress((void**)&dinv, g_dinv);
    cudaGetSymbolAddress((void**)&cnt,  g_cnt);
    cudaGetSymbolAddress((void**)&rowp, g_rowp);
    cudaGetSymbolAddress((void**)&cursor, g_cursor);
    cudaGetSymbolAddress((void**)&bsum, g_bsum);
    cudaGetSymbolAddress((void**)&csr_src,  g_csr_src);
    cudaGetSymbolAddress((void**)&wt,   g_wt);
    cudaGetSymbolAddress((void**)&hw,   g_hw);
    cudaGetSymbolAddress((void**)&h,    g_h);
    cudaGetSymbolAddress((void**)&temp, g_temp);

    // --- side stream + events + attributes (created once) ---
    static cudaStream_t sSide = nullptr;
    static cudaEvent_t evRoot = nullptr, evDinv = nullptr, evCSR = nullptr;
    if (!sSide) {
        cudaStreamCreateWithFlags(&sSide, cudaStreamNonBlocking);
        cudaEventCreateWithFlags(&evRoot, cudaEventDisableTiming);
        cudaEventCreateWithFlags(&evDinv, cudaEventDisableTiming);
        cudaEventCreateWithFlags(&evCSR,  cudaEventDisableTiming);
        cudaFuncSetAttribute(head_fused_kernel,
            cudaFuncAttributeMaxDynamicSharedMemorySize, HF_SMEM);
    }

    const int T = 256;
    int e8Blocks = (int)(((size_t)(EE + 7) / 8 + T - 1) / T);

    // ---- fork: CSR build on side stream ----
    cudaEventRecord(evRoot, 0);
    cudaStreamWaitEvent(sSide, evRoot, 0);
    cudaMemsetAsync(cnt, 0, NN * sizeof(int), sSide);
    cnt_count_kernel<<<e8Blocks, T, 0, sSide>>>(dstE, cnt);
    dinv_kernel<<<(NN + T - 1) / T, T, 0, sSide>>>(cnt, dinv);
    cudaEventRecord(evDinv, sSide);
    scan_block_kernel<<<NBLK_SCAN, SCAN_B, 0, sSide>>>(cnt, rowp, bsum);
    scan_bsum_kernel<<<1, 128, 0, sSide>>>(bsum);
    scan_add_kernel<<<(NN + T - 1) / T, T, 0, sSide>>>(rowp, bsum, cursor);
    scatter_kernel<<<e8Blocks, T, 0, sSide>>>(srcE, dstE, cursor, csr_src);
    cudaEventRecord(evCSR, sSide);

    // ---- main stream: weights + CSR-independent GEMMs ----
    WtParams WP;
    WP.seg[0] = { W1,  128, 128, OFF_W1 };
    WP.seg[1] = { W2,  128, 128, OFF_W2 };
    WP.seg[2] = { W3,  128, 128, OFF_W3 };
    WP.seg[3] = { Wf,  128, 128, OFF_WF };
    WP.seg[4] = { Wh1, 448, 256, OFF_WH1 };
    WP.seg[5] = { Wh2, 256, 128, OFF_WH2 };
    WP.seg[6] = { Wh3, 128, 64,  OFF_WH3 };
    wt_build_kernel<<<(WT_TOTAL + T - 1) / T, T>>>(WP, wt);

    dim3 blk(256);
    dim3 gNode(1, (NN + 127) / 128);
    dim3 gHead(1, (BB + 127) / 128);
    int aggBlocks = (NN + 7) / 8;

    GParams P = {};
    P.h = h; P.temp = temp;
    P.day_table = day_table; P.time_table = time_table; P.mode_table = mode_table;
    P.orig = origin_ids; P.dest = dest_ids;
    P.day_ids = day_ids; P.time_ids = time_ids; P.mode_ids = mode_ids;

    // temporal GEMM: fills the gap while side computes degrees
    tc_gemm_kernel<3><<<gHead, blk>>>(P, wt + OFF_WF, bf, nullptr, temp, BB, HH, HH, 1);

    // GEMM1 needs dinv only
    cudaStreamWaitEvent(0, evDinv, 0);
    GParams Pa = P; Pa.A = x;
    tc_gemm_kernel<0><<<gNode, blk>>>(Pa, wt + OFF_W1, nullptr, dinv, hw, NN, FF, HH, 2);

    // join: aggregation needs the CSR
    cudaStreamWaitEvent(0, evCSR, 0);

    // --- GCN layers ---
    agg_fused_kernel<<<aggBlocks, T>>>(rowp, csr_src, dinv, hw, b1, h);
    Pa.A = h;
    tc_gemm_kernel<1><<<gNode, blk>>>(Pa, wt + OFF_W2, nullptr, dinv, hw, NN, HH, HH, 2);
    agg_fused_kernel<<<aggBlocks, T>>>(rowp, csr_src, dinv, hw, b2, h);
    tc_gemm_kernel<1><<<gNode, blk>>>(Pa, wt + OFF_W3, nullptr, dinv, hw, NN, HH, HH, 2);
    agg_fused_kernel<<<aggBlocks, T>>>(rowp, csr_src, dinv, hw, b3, h);

    // --- fully fused prediction head ---
    head_fused_kernel<<<BB / 128, blk, HF_SMEM>>>(P,
        wt + OFF_WH1, wt + OFF_WH2, wt + OFF_WH3,
        bh1, bh2, bh3, Wh4, bh4, out);
}